// round 15
// baseline (speedup 1.0000x reference)
#include <cuda_runtime.h>
#include <cuda_fp16.h>
#include <math.h>
#include <stdint.h>

constexpr int B_  = 32;
constexpr int TD  = 64;
constexpr int TE  = 256;
constexpr int H_  = 512;
constexpr int E_  = 512;
constexpr int V_  = 32000;
constexpr int L_  = 2;
constexpr int NH  = 8;
constexpr int DH  = 64;
constexpr int BTV = B_ * TD * V_;
constexpr int LBH = L_ * B_ * H_;

constexpr int NBLK = 128;
constexpr int NTHR = 512;

// ---------------- scratch (device globals) ----------------------------------
__device__ __align__(16) float g_Kh  [B_ * TE * H_];
__device__ __align__(16) float g_Kh2 [B_ * NH * DH * TE];
__device__ __align__(16) float g_Vh  [B_ * TE * H_];
__device__ __align__(16) float g_eprojT[TD * H_ * B_];   // [t][k][b]
__device__ __align__(16) float g_Wcombt[H_ * H_];
__device__ __align__(16) float g_hAT[L_ * H_ * B_];      // [l][k][b]
__device__ __align__(16) float g_hBT[L_ * H_ * B_];
__device__ __align__(16) float g_qT  [H_ * B_];
__device__ __align__(16) float g_ctxT[H_ * B_];
__device__ __align__(16) float g_xraT[H_ * B_];
__device__ __align__(16) float g_xrbT[H_ * B_];
__device__ int g_bar;

__device__ __align__(16) __half g_enc_h [B_ * TE * 2 * H_];
__device__ __align__(16) __half g_Wkt_h [H_ * 2 * H_];
__device__ __align__(16) __half g_Wkt_l [H_ * 2 * H_];
__device__ __align__(16) __half g_Wvt_h [H_ * 2 * H_];
__device__ __align__(16) __half g_Wvt_l [H_ * 2 * H_];
__device__ __align__(16) __half g_Wint_h[H_ * H_];
__device__ __align__(16) __half g_Wint_l[H_ * H_];
__device__ __align__(16) __half g_Wdt_h [V_ * H_];
__device__ __align__(16) __half g_Wdt_l [V_ * H_];
__device__ __align__(16) __half g_eseq_h[TD * B_ * E_];
__device__ __align__(16) __half g_eseq_l[TD * B_ * E_];
__device__ __align__(16) __half g_ys_h  [TD * B_ * H_];

// ======================= helpers =============================================
__device__ __forceinline__ uint32_t smem_u32(const void* p) {
    uint32_t a;
    asm("{ .reg .u64 t; cvta.to.shared.u64 t, %1; cvt.u32.u64 %0, t; }"
        : "=r"(a) : "l"(p));
    return a;
}
__device__ __forceinline__ void ldsm4(uint32_t (&r)[4], uint32_t addr) {
    asm volatile("ldmatrix.sync.aligned.m8n8.x4.shared.b16 {%0,%1,%2,%3}, [%4];"
        : "=r"(r[0]), "=r"(r[1]), "=r"(r[2]), "=r"(r[3]) : "r"(addr));
}
__device__ __forceinline__ void mma16816(float (&d)[4], const uint32_t (&a)[4],
                                         uint32_t b0, uint32_t b1) {
    asm volatile(
        "mma.sync.aligned.m16n8k16.row.col.f32.f16.f16.f32 "
        "{%0,%1,%2,%3}, {%4,%5,%6,%7}, {%8,%9}, {%0,%1,%2,%3};"
        : "+f"(d[0]), "+f"(d[1]), "+f"(d[2]), "+f"(d[3])
        : "r"(a[0]), "r"(a[1]), "r"(a[2]), "r"(a[3]), "r"(b0), "r"(b1));
}
#define CPA16(dst, src) \
    asm volatile("cp.async.cg.shared.global [%0], [%1], 16;" \
                 :: "r"(dst), "l"(src) : "memory")
#define CP_COMMIT() asm volatile("cp.async.commit_group;" ::: "memory")
#define CP_WAIT1()  asm volatile("cp.async.wait_group 1;" ::: "memory")
#define CP_WAIT0()  asm volatile("cp.async.wait_group 0;" ::: "memory")

__device__ __forceinline__ float fsig(float x) {
    return 1.f / (1.f + __expf(-x));
}
__device__ __forceinline__ float ftanh(float x) {
    return 2.f / (1.f + __expf(-2.f * x)) - 1.f;
}
__device__ __forceinline__ void hsplit(float x, __half& h, __half& l) {
    h = __float2half_rn(x);
    l = __float2half_rn(x - __half2float(h));
}

// ============ HMMA compensated-fp16 GEMM (cp.async 2-stage pipeline) =========
// passes==3: D = Ah*Bh + Ah*Bl + Al*Bh ; passes==2: D = Ah*Bh + Ah*Bl
constexpr int BKg  = 32;
constexpr int LDSg = BKg + 8;
constexpr int GMSZ = 128 * LDSg;
constexpr int GSSZ = 4 * GMSZ;
constexpr int GEMM_DSM_BYTES = 2 * GSSZ * 2;

__device__ __forceinline__ void mma_gemm_body(
    char* dsm,
    int M, int N, int K,
    const __half* __restrict__ Ah, const __half* __restrict__ Al,
    const __half* __restrict__ Bh, const __half* __restrict__ Bl,
    float* __restrict__ C, const float* __restrict__ bias, int mode,
    int bx, int by, int passes)
{
    __half* sb = (__half*)dsm;
    const uint32_t sbase = smem_u32(sb);

    const int tid = threadIdx.x, lane = tid & 31, wid = tid >> 5;
    const int wm = wid >> 1, wn = wid & 1;
    const int n0 = bx * 128, m0 = by * 128;

    float acc[2][8][4];
#pragma unroll
    for (int i = 0; i < 2; i++)
#pragma unroll
        for (int j = 0; j < 8; j++)
#pragma unroll
            for (int k = 0; k < 4; k++) acc[i][j][k] = 0.f;

    const int lrow = tid >> 2;
    const int lcol = (tid & 3) * 8;
    const int nch = K >> 5;

    auto issue = [&](int kc, int st) {
        const int kb = kc << 5;
#pragma unroll
        for (int h = 0; h < 2; h++) {
            int row = lrow + h * 64;
            const __half* pa = Ah + (size_t)(m0 + row) * K + kb + lcol;
            const __half* pb = Bh + (size_t)(n0 + row) * K + kb + lcol;
            const __half* pq = Bl + (size_t)(n0 + row) * K + kb + lcol;
            uint32_t d = sbase + (uint32_t)(st * GSSZ + row * LDSg + lcol) * 2;
            CPA16(d,                pa);
            CPA16(d + 2 * GMSZ * 2, pb);
            CPA16(d + 3 * GMSZ * 2, pq);
            if (passes == 3) {
                const __half* pl = Al + (size_t)(m0 + row) * K + kb + lcol;
                CPA16(d + GMSZ * 2, pl);
            }
        }
        CP_COMMIT();
    };

    issue(0, 0);
    for (int kc = 0; kc < nch; kc++) {
        const int st = kc & 1;
        if (kc + 1 < nch) {
            issue(kc + 1, st ^ 1);
            CP_WAIT1();
        } else {
            CP_WAIT0();
        }
        __syncthreads();
        __half* sAh = sb + st * GSSZ;
        __half* sAl = sAh + GMSZ;
        __half* sBh = sAh + 2 * GMSZ;
        __half* sBl = sAh + 3 * GMSZ;

#pragma unroll
        for (int ks = 0; ks < BKg; ks += 16) {
            uint32_t ah[2][4], al[2][4];
            const uint32_t fcol = ks + (lane >> 4) * 8;
#pragma unroll
            for (int mi = 0; mi < 2; mi++) {
                uint32_t arow = wm * 32 + mi * 16 + (lane & 15);
                ldsm4(ah[mi], smem_u32(&sAh[arow * LDSg + fcol]));
                if (passes == 3)
                    ldsm4(al[mi], smem_u32(&sAl[arow * LDSg + fcol]));
            }
#pragma unroll
            for (int nj = 0; nj < 4; nj++) {
                uint32_t brow = wn * 64 + nj * 16 + (lane & 15);
                uint32_t bh[4], bl[4];
                ldsm4(bh, smem_u32(&sBh[brow * LDSg + fcol]));
                ldsm4(bl, smem_u32(&sBl[brow * LDSg + fcol]));
#pragma unroll
                for (int mi = 0; mi < 2; mi++) {
                    mma16816(acc[mi][2 * nj],     ah[mi], bh[0], bh[2]);
                    mma16816(acc[mi][2 * nj + 1], ah[mi], bh[1], bh[3]);
                    mma16816(acc[mi][2 * nj],     ah[mi], bl[0], bl[2]);
                    mma16816(acc[mi][2 * nj + 1], ah[mi], bl[1], bl[3]);
                    if (passes == 3) {
                        mma16816(acc[mi][2 * nj],     al[mi], bh[0], bh[2]);
                        mma16816(acc[mi][2 * nj + 1], al[mi], bh[1], bh[3]);
                    }
                }
            }
        }
        __syncthreads();
    }

#pragma unroll
    for (int mi = 0; mi < 2; mi++) {
        int row = m0 + wm * 32 + mi * 16 + (lane >> 2);
#pragma unroll
        for (int nt = 0; nt < 8; nt++) {
            int col = n0 + wn * 64 + nt * 8 + (lane & 3) * 2;
            float bb0 = bias ? bias[col] : 0.f;
            float bb1 = bias ? bias[col + 1] : 0.f;
            float2 v0 = make_float2(acc[mi][nt][0] + bb0, acc[mi][nt][1] + bb1);
            float2 v1 = make_float2(acc[mi][nt][2] + bb0, acc[mi][nt][3] + bb1);
            if (mode == 0) {
                *(float2*)&C[(size_t)row * N + col] = v0;
                *(float2*)&C[(size_t)(row + 8) * N + col] = v1;
            } else if (mode == 1) {
                int t0 = row >> 5, b0v_ = row & 31;
                int t1 = (row + 8) >> 5, b1v_ = (row + 8) & 31;
                *(float2*)&C[(size_t)b0v_ * (TD * V_) + (size_t)t0 * V_ + col] = v0;
                *(float2*)&C[(size_t)b1v_ * (TD * V_) + (size_t)t1 * V_ + col] = v1;
            } else {  // mode 2: eprojT[(t*512 + col)*32 + b]
                int t0 = row >> 5, b0v_ = row & 31;
                int t1 = (row + 8) >> 5, b1v_ = (row + 8) & 31;
                C[((size_t)t0 * 512 + col)     * 32 + b0v_] = v0.x;
                C[((size_t)t0 * 512 + col + 1) * 32 + b0v_] = v0.y;
                C[((size_t)t1 * 512 + col)     * 32 + b1v_] = v1.x;
                C[((size_t)t1 * 512 + col + 1) * 32 + b1v_] = v1.y;
            }
        }
    }
}

__global__ __launch_bounds__(256, 2) void mma_gemm_kernel(
    int M, int N, int K,
    const __half* __restrict__ Ah, const __half* __restrict__ Al,
    const __half* __restrict__ Bh, const __half* __restrict__ Bl,
    float* __restrict__ C, const float* __restrict__ bias, int mode, int passes)
{
    extern __shared__ __align__(16) char dsm[];
    mma_gemm_body(dsm, M, N, K, Ah, Al, Bh, Bl, C, bias, mode,
                  blockIdx.x, blockIdx.y, passes);
}

// fp32 SIMT GEMM body (512x512x512, transposed write) for Wcomb^T
__device__ void sgemm_tr_body(float* As, float* Bs,
    const float* __restrict__ A, const float* __restrict__ B,
    float* __restrict__ C, int bx, int by)
{
    const int tid = threadIdx.x;
    const float* Aptr = A + (size_t)(by * 128 + (tid >> 1)) * 512 + (tid & 1) * 4;
    const float* Bptr = B + (size_t)(tid >> 5) * 512 + bx * 128 + (tid & 31) * 4;
    const int ty = tid >> 4, tx = tid & 15;
    float acc[8][8];
#pragma unroll
    for (int i = 0; i < 8; i++)
#pragma unroll
        for (int j = 0; j < 8; j++) acc[i][j] = 0.f;
    for (int k0 = 0; k0 < 512; k0 += 8) {
        float4 av = *(const float4*)(Aptr + k0);
        float4 bv = *(const float4*)(Bptr + (size_t)k0 * 512);
        __syncthreads();
        const int ar_ = tid >> 1, ac_ = (tid & 1) * 4;
        As[(ac_ + 0) * 132 + ar_] = av.x; As[(ac_ + 1) * 132 + ar_] = av.y;
        As[(ac_ + 2) * 132 + ar_] = av.z; As[(ac_ + 3) * 132 + ar_] = av.w;
        *(float4*)&Bs[(tid >> 5) * 132 + (tid & 31) * 4] = bv;
        __syncthreads();
#pragma unroll
        for (int kk = 0; kk < 8; kk++) {
            float ar[8], br[8];
            *(float4*)(ar)     = *(float4*)&As[kk * 132 + ty * 4];
            *(float4*)(ar + 4) = *(float4*)&As[kk * 132 + ty * 4 + 64];
            *(float4*)(br)     = *(float4*)&Bs[kk * 132 + tx * 4];
            *(float4*)(br + 4) = *(float4*)&Bs[kk * 132 + tx * 4 + 64];
#pragma unroll
            for (int i = 0; i < 8; i++)
#pragma unroll
                for (int j = 0; j < 8; j++) acc[i][j] += ar[i] * br[j];
        }
    }
#pragma unroll
    for (int i = 0; i < 8; i++) {
        int m = by * 128 + ty * 4 + (i & 3) + (i >> 2) * 64;
#pragma unroll
        for (int j = 0; j < 8; j++) {
            int n = bx * 128 + tx * 4 + (j & 3) + (j >> 2) * 64;
            C[(size_t)n * 512 + m] = acc[i][j];
        }
    }
}

__global__ __launch_bounds__(256, 2) void mma_batched_kernel(
    const __half* __restrict__ encH,
    const __half* __restrict__ WkH,  const __half* __restrict__ WkL,
    const __half* __restrict__ WvH,  const __half* __restrict__ WvL,
    const __half* __restrict__ esH,  const __half* __restrict__ esL,
    const __half* __restrict__ WinH, const __half* __restrict__ WinL,
    float* __restrict__ Kh, float* __restrict__ Vh, float* __restrict__ eprojT,
    const float* __restrict__ Wo, const float* __restrict__ Win,
    float* __restrict__ WcombT)
{
    extern __shared__ __align__(16) char dsm[];
    int z = blockIdx.z;
    if (z == 0) {
        mma_gemm_body(dsm, B_ * TE, H_, 2 * H_,
                      encH, nullptr, WkH, WkL, Kh, nullptr, 0, blockIdx.x, blockIdx.y, 2);
    } else if (z == 1) {
        mma_gemm_body(dsm, B_ * TE, H_, 2 * H_,
                      encH, nullptr, WvH, WvL, Vh, nullptr, 0, blockIdx.x, blockIdx.y, 2);
    } else if (z == 2) {
        if (blockIdx.y >= (TD * B_) / 128) return;
        mma_gemm_body(dsm, TD * B_, H_, E_,
                      esH, esL, WinH, WinL, eprojT, nullptr, 2, blockIdx.x, blockIdx.y, 3);
    } else {
        if (blockIdx.x >= 4 || blockIdx.y >= 4) return;
        sgemm_tr_body((float*)dsm, (float*)dsm + 1056, Wo, Win, WcombT,
                      blockIdx.x, blockIdx.y);
    }
}

// ---------------- fused prep -------------------------------------------------
__device__ void tconv_body(const float* __restrict__ W, int K, int N, int row_off,
                           __half* __restrict__ oh, __half* __restrict__ ol,
                           int bxx, int byy, float* t)
{
    int tx = threadIdx.x & 31, ty = threadIdx.x >> 5;
    int n0 = bxx * 32, k0 = byy * 32;
    for (int ky = ty; ky < 32; ky += 8)
        t[ky * 33 + tx] = W[(size_t)(row_off + k0 + ky) * N + n0 + tx];
    __syncthreads();
    for (int ny = ty; ny < 32; ny += 8) {
        float v = t[tx * 33 + ny];
        __half h, l; hsplit(v, h, l);
        size_t o = (size_t)(n0 + ny) * K + k0 + tx;
        oh[o] = h; ol[o] = l;
    }
}

constexpr int SEG0 = (B_ * TE * 2 * H_) / 4 / 256;   // 8192
constexpr int SEG1 = SEG0 + 512;
constexpr int SEG2 = SEG1 + 512;
constexpr int SEG3 = SEG2 + 256;
constexpr int SEG4 = SEG3 + 16000;
constexpr int SEG5 = SEG4 + 2048;
constexpr int SEG6 = SEG5 + 128;
constexpr int PREP_BLOCKS = SEG6;

__global__ __launch_bounds__(256) void prep_all_kernel(
    const float* __restrict__ enc, const float* __restrict__ Wk,
    const float* __restrict__ Wv, const float* __restrict__ Win,
    const float* __restrict__ Wd, const int* __restrict__ x,
    const float* __restrict__ emb, const float* __restrict__ h0)
{
    __shared__ float t[32 * 33];
    int blk = blockIdx.x, tid = threadIdx.x;
    if (blk == 0 && tid == 0) g_bar = 0;
    if (blk < SEG0) {
        int i = blk * 256 + tid;
        float4 v = ((const float4*)enc)[i];
        ((__half2*)g_enc_h)[2 * i]     = __half2(__float2half_rn(v.x), __float2half_rn(v.y));
        ((__half2*)g_enc_h)[2 * i + 1] = __half2(__float2half_rn(v.z), __float2half_rn(v.w));
    } else if (blk < SEG1) {
        int i = blk - SEG0;
        tconv_body(Wk, 2 * H_, H_, 0, g_Wkt_h, g_Wkt_l, i % 16, i / 16, t);
    } else if (blk < SEG2) {
        int i = blk - SEG1;
        tconv_body(Wv, 2 * H_, H_, 0, g_Wvt_h, g_Wvt_l, i % 16, i / 16, t);
    } else if (blk < SEG3) {
        int i = blk - SEG2;
        tconv_body(Win, H_, H_, 512, g_Wint_h, g_Wint_l, i % 16, i / 16, t);
    } else if (blk < SEG4) {
        int i = blk - SEG3;
        tconv_body(Wd, H_, V_, 0, g_Wdt_h, g_Wdt_l, i % 1000, i / 1000, t);
    } else if (blk < SEG5) {
        int r = blk - SEG4;
        int tt = r >> 5, b = r & 31;
        int tok = x[b * TD + tt];
        const float* src = emb + (size_t)tok * E_;
        for (int i = tid; i < E_; i += 256) {
            __half h, l; hsplit(src[i], h, l);
            g_eseq_h[(size_t)r * E_ + i] = h;
            g_eseq_l[(size_t)r * E_ + i] = l;
        }
    } else {
        int i = (blk - SEG5) * 256 + tid;     // 0..32767 over [l][b][k]
        int l = i >> 14, b = (i >> 9) & 31, k = i & 511;
        g_hAT[((size_t)l * 512 + k) * 32 + b] = h0[i];
    }
}

// ---------------- transpose Kh (b,s,h,d) -> Kh2 (b,h,d,s) --------------------
__global__ void transpose_k_kernel()
{
    __shared__ float t[32][33];
    int bh = blockIdx.x;
    int b = bh >> 3, h = bh & 7;
    int s0 = blockIdx.y * 32, d0 = blockIdx.z * 32;
    for (int yy = threadIdx.y; yy < 32; yy += 8)
        t[yy][threadIdx.x] = g_Kh[((size_t)(b * 256 + s0 + yy) * 8 + h) * 64 + d0 + threadIdx.x];
    __syncthreads();
    for (int yy = threadIdx.y; yy < 32; yy += 8)
        g_Kh2[((size_t)(bh) * 64 + d0 + yy) * 256 + s0 + threadIdx.x] = t[threadIdx.x][yy];
}

__global__ void hfinal_kernel(float* __restrict__ dst)
{
    int i = blockIdx.x * blockDim.x + threadIdx.x;
    if (i < LBH) {
        int l = i >> 14, b = (i >> 9) & 31, k = i & 511;
        dst[i] = g_hAT[((size_t)l * 512 + k) * 32 + b];
    }
}

// =================== PERSISTENT SCAN KERNEL ==================================
constexpr int OFF_W   = 0;        // 24576: w[l][k][24] (ih gamma-folded)
constexpr int OFF_WC  = 24576;    // 2048:  Wcomb slice [k][4j]
constexpr int OFF_WQ  = 26624;    // 2048:  Wq slice [k][4j]
constexpr int OFF_GP  = 28672;    // 6144:  partials; attention alias (2x576)
constexpr int OFF_HH  = 34816;    // 12288: hh partials [l][6144]
constexpr int OFF_GS  = 47104;    // 1024:  stats partials
constexpr int OFF_S   = 48128;    // 24
constexpr int OFF_BC  = 48152;    // 24
constexpr int OFF_SB  = 48176;    // 48
constexpr int SCAN_SMEM_FLOATS = 48256;   // 193024 B

__device__ __forceinline__ void bar_arrive(int& epoch) {
    __syncthreads();
    epoch += NBLK;
    if (threadIdx.x == 0) {
        int* p = &g_bar;
        asm volatile("red.release.gpu.global.add.s32 [%0], 1;" :: "l"(p) : "memory");
    }
}
__device__ __forceinline__ void bar_wait(int epoch) {
    if (threadIdx.x == 0) {
        int* p = &g_bar;
        int v;
        do {
            asm volatile("ld.acquire.gpu.global.s32 %0, [%1];" : "=r"(v) : "l"(p) : "memory");
        } while (v < epoch);
    }
    __syncthreads();
}
__device__ __forceinline__ void grid_bar(int& epoch) {
    bar_arrive(epoch);
    bar_wait(epoch);
}

__global__ __launch_bounds__(NTHR, 1) void scan_kernel(
    const float* __restrict__ Wq,  const int* __restrict__ vlen,
    const float* __restrict__ Wih, const float* __restrict__ Whh,
    const float* __restrict__ bih, const float* __restrict__ bhh,
    const float* __restrict__ lng, const float* __restrict__ lnb,
    const float* __restrict__ alph)
{
    extern __shared__ float sm[];
    float* w    = sm + OFF_W;
    float* wcs  = sm + OFF_WC;
    float* wqs  = sm + OFF_WQ;
    float* gp   = sm + OFF_GP;
    float* at   = sm + OFF_GP;
    float* gph  = sm + OFF_HH;
    float* gs1  = sm + OFF_GS;
    float* gs2  = sm + OFF_GS + 512;
    float* sS   = sm + OFF_S;
    float* sBc  = sm + OFF_BC;
    float* sbias = sm + OFF_SB;

    const int tid = threadIdx.x, lane = tid & 31, wid = tid >> 5;
    const int blk = blockIdx.x;
    int epoch = 0;

    // ---- one-time weight staging ----
    for (int i = tid; i < 24576; i += NTHR) {
        int unit = i >> 9, k = i & 511;
        int l = unit / 24, idx = unit % 24;
        int pass = idx / 12, r = idx % 12;
        int g = r >> 2, j = r & 3;
        const float* src = (pass == 0)
            ? (Wih + ((size_t)l * 1536 + g * 512 + blk * 4 + j) * 512)
            : (Whh + ((size_t)l * 1536 + g * 512 + blk * 4 + j) * 512);
        w[((l * 512 + k) * 24) + pass * 12 + g * 4 + j] = src[k];
    }
    for (int i = tid; i < 2048; i += NTHR) {
        int k = i >> 2, j = i & 3;
        wcs[i] = g_Wcombt[(size_t)(blk * 4 + j) * 512 + k];
        wqs[i] = Wq[(size_t)k * 512 + blk * 4 + j];
    }
    if (tid < 48) {
        int l = tid / 24, r = tid % 24;
        int j = r / 6, g6 = r % 6;
        int jg = blk * 4 + j;
        sbias[tid] = (g6 < 3) ? bih[l * 1536 + g6 * 512 + jg]
                              : bhh[l * 1536 + (g6 - 3) * 512 + jg];
    }
    __syncthreads();
    if (tid < 24) {
        int l = tid / 12, idx = tid % 12;
        float s = 0.f, bc = 0.f;
        for (int k = 0; k < 512; k++) {
            float rw = w[((l * 512 + k) * 24) + idx];
            s  += lng[l * 512 + k] * rw;
            bc += lnb[l * 512 + k] * rw;
        }
        sS[tid] = s;
        sBc[tid] = bc;
    }
    __syncthreads();
    for (int i = tid; i < 12288; i += NTHR) {
        int l = i / 6144, r = i % 6144;
        int k = r / 12, idx = r % 12;
        w[((l * 512 + k) * 24) + idx] *= lng[l * 512 + k];
    }
    __syncthreads();

    for (int t = 0; t < TD; t++) {
        const float* hinT  = (t & 1) ? g_hBT : g_hAT;
        float*       houtT = (t & 1) ? g_hAT : g_hBT;

        // ===== phase 0: qT = hlast @ Wq (4 cols/block, SMEM Wq slice) ========
        {
            const float* h1 = hinT + 512 * 32;   // layer 1, [k][b]
            int kc = wid * 32;
            float a0 = 0.f, a1 = 0.f, a2 = 0.f, a3 = 0.f;
#pragma unroll 8
            for (int kk = 0; kk < 32; kk++) {
                int k = kc + kk;
                float xv = h1[k * 32 + lane];
                float4 wv = *(const float4*)(wqs + k * 4);
                a0 += wv.x * xv; a1 += wv.y * xv; a2 += wv.z * xv; a3 += wv.w * xv;
            }
            gp[(wid * 4 + 0) * 32 + lane] = a0;
            gp[(wid * 4 + 1) * 32 + lane] = a1;
            gp[(wid * 4 + 2) * 32 + lane] = a2;
            gp[(wid * 4 + 3) * 32 + lane] = a3;
            __syncthreads();
            if (tid < 128) {
                int j = tid >> 5, b = tid & 31, jg = blk * 4 + j;
                float v = 0.f;
#pragma unroll
                for (int w2 = 0; w2 < 16; w2++) v += gp[(w2 * 4 + j) * 32 + b];
                g_qT[jg * 32 + b] = v;
            }
        }
        bar_arrive(epoch);

        // ===== overlap window: hh matvecs for BOTH layers (depend on hinT) ==
        {
            const int kc = wid * 32;
#pragma unroll
            for (int l = 0; l < 2; l++) {
                const float* hTl = hinT + (size_t)l * 512 * 32;
                float acc[12];
#pragma unroll
                for (int i = 0; i < 12; i++) acc[i] = 0.f;
                const float* wrow = w + ((size_t)(l * 512 + kc) * 24) + 12;
#pragma unroll 8
                for (int kk = 0; kk < 32; kk++) {
                    float xv = hTl[(kc + kk) * 32 + lane];
                    float4 w0 = *(const float4*)(wrow + kk * 24 + 0);
                    float4 w1 = *(const float4*)(wrow + kk * 24 + 4);
                    float4 w2 = *(const float4*)(wrow + kk * 24 + 8);
                    acc[0] += w0.x * xv; acc[1] += w0.y * xv; acc[2] += w0.z * xv; acc[3] += w0.w * xv;
                    acc[4] += w1.x * xv; acc[5] += w1.y * xv; acc[6] += w1.z * xv; acc[7] += w1.w * xv;
                    acc[8] += w2.x * xv; acc[9] += w2.y * xv; acc[10] += w2.z * xv; acc[11] += w2.w * xv;
                }
#pragma unroll
                for (int i = 0; i < 12; i++)
                    gph[l * 6144 + (wid * 12 + i) * 32 + lane] = acc[i];
            }
        }
        bar_wait(epoch);

        // ===== phase 1: attention (2 bh-units per block) =====================
        {
            int grp = tid >> 8, lt = tid & 255;
            int u = blk * 2 + grp;
            int b = u >> 3, h = u & 7;
            float* sq_ = at + grp * 576;
            float* sp_ = sq_ + 64;
            float* rd_ = sp_ + 256;

            if (lt < 64) sq_[lt] = g_qT[(h * 64 + lt) * 32 + b];
            __syncthreads();

            float sc = -1e6f;
            int vl = vlen[b];
            if (lt < vl) {
                float a0 = 0.f, a1 = 0.f;
                const float* kp = g_Kh2 + (size_t)u * 64 * 256 + lt;
#pragma unroll 8
                for (int dd = 0; dd < 64; dd += 2) {
                    a0 += sq_[dd]     * kp[dd * 256];
                    a1 += sq_[dd + 1] * kp[(dd + 1) * 256];
                }
                sc = (a0 + a1) * 0.125f;
            }
            int wg = lt >> 5;
            float m = sc;
#pragma unroll
            for (int o = 16; o; o >>= 1) m = fmaxf(m, __shfl_xor_sync(0xffffffffu, m, o));
            if ((lt & 31) == 0) rd_[wg] = m;
            __syncthreads();
            float mx = rd_[0];
#pragma unroll
            for (int i = 1; i < 8; i++) mx = fmaxf(mx, rd_[i]);
            float p = __expf(sc - mx);
            float s = p;
#pragma unroll
            for (int o = 16; o; o >>= 1) s += __shfl_xor_sync(0xffffffffu, s, o);
            if ((lt & 31) == 0) rd_[8 + wg] = s;
            __syncthreads();
            float sum = rd_[8];
#pragma unroll
            for (int i = 1; i < 8; i++) sum += rd_[8 + i];
            sp_[lt] = p / sum;
            __syncthreads();

            int d = lt & 63, c = lt >> 6;
            {
                // skip s >= vlen: those sp_ are exactly 0 (exp underflow)
                int lim = vl - c * 64;
                if (lim > 64) lim = 64;
                float a0 = 0.f, a1 = 0.f;
                const float* vp = g_Vh + ((size_t)(b * 256 + c * 64) * 8 + h) * 64 + d;
                int ss = 0;
#pragma unroll 4
                for (; ss + 1 < lim; ss += 2) {
                    a0 += sp_[c * 64 + ss]     * vp[(size_t)ss * 512];
                    a1 += sp_[c * 64 + ss + 1] * vp[(size_t)(ss + 1) * 512];
                }
                if (ss < lim) a0 += sp_[c * 64 + ss] * vp[(size_t)ss * 512];
                rd_[lt] = a0 + a1;
            }
            __syncthreads();
            if (lt < 64)
                g_ctxT[(h * 64 + lt) * 32 + b] =
                    rd_[lt] + rd_[lt + 64] + rd_[lt + 128] + rd_[lt + 192];
        }
        grid_bar(epoch);

        // ===== phase 2: xr = ctx @ Wcomb + eprojT ============================
        {
            int kc = wid * 32;
            float a0 = 0.f, a1 = 0.f, a2 = 0.f, a3 = 0.f;
#pragma unroll 8
            for (int kk = 0; kk < 32; kk++) {
                int k = kc + kk;
                float xv = g_ctxT[k * 32 + lane];
                float4 wv = *(const float4*)(wcs + k * 4);
                a0 += wv.x * xv; a1 += wv.y * xv; a2 += wv.z * xv; a3 += wv.w * xv;
            }
            gp[(wid * 4 + 0) * 32 + lane] = a0;
            gp[(wid * 4 + 1) * 32 + lane] = a1;
            gp[(wid * 4 + 2) * 32 + lane] = a2;
            gp[(wid * 4 + 3) * 32 + lane] = a3;
        }
        __syncthreads();
        if (tid < 128) {
            int j = tid >> 5, b = tid & 31, jg = blk * 4 + j;
            float v = 0.f;
#pragma unroll
            for (int w2 = 0; w2 < 16; w2++) v += gp[(w2 * 4 + j) * 32 + b];
            v += g_eprojT[((size_t)t * 512 + jg) * 32 + b];
            g_xraT[jg * 32 + b] = v;
        }
        grid_bar(epoch);

        // ===== phases 3,4: GRU layers (ih + combine) =========================
        for (int l = 0; l < 2; l++) {
            const float* xrT = (l == 0) ? g_xraT : g_xrbT;
            const float* hTl = hinT + (size_t)l * 512 * 32;
            float* hToutl = houtT + (size_t)l * 512 * 32;

            const int kc = wid * 32;
            {
                float acc[12];
#pragma unroll
                for (int i = 0; i < 12; i++) acc[i] = 0.f;
                float s1 = 0.f, s2 = 0.f;
                const float* wrow = w + ((size_t)(l * 512 + kc) * 24);
#pragma unroll 8
                for (int kk = 0; kk < 32; kk++) {
                    float xv = xrT[(kc + kk) * 32 + lane];
                    s1 += xv; s2 += xv * xv;
                    float4 w0 = *(const float4*)(wrow + kk * 24 + 0);
                    float4 w1 = *(const float4*)(wrow + kk * 24 + 4);
                    float4 w2 = *(const float4*)(wrow + kk * 24 + 8);
                    acc[0] += w0.x * xv; acc[1] += w0.y * xv; acc[2] += w0.z * xv; acc[3] += w0.w * xv;
                    acc[4] += w1.x * xv; acc[5] += w1.y * xv; acc[6] += w1.z * xv; acc[7] += w1.w * xv;
                    acc[8] += w2.x * xv; acc[9] += w2.y * xv; acc[10] += w2.z * xv; acc[11] += w2.w * xv;
                }
#pragma unroll
                for (int i = 0; i < 12; i++)
                    gp[(wid * 12 + i) * 32 + lane] = acc[i];
                gs1[wid * 32 + lane] = s1;
                gs2[wid * 32 + lane] = s2;
            }
            __syncthreads();
            if (tid < 128) {
                int j = tid >> 5, b = tid & 31, jg = blk * 4 + j;
                float s1 = 0.f, s2 = 0.f;
#pragma unroll
                for (int w2 = 0; w2 < 16; w2++) {
                    s1 += gs1[w2 * 32 + b];
                    s2 += gs2[w2 * 32 + b];
                }
                float mu = s1 * (1.f / 512.f);
                float var = s2 * (1.f / 512.f) - mu * mu;
                float rsv = rsqrtf(var + 1e-5f);

                float Dir = 0.f, Diz = 0.f, Dig = 0.f, hr = 0.f, hz = 0.f, hg = 0.f;
#pragma unroll
                for (int w2 = 0; w2 < 16; w2++) {
                    const float* g0 = gp + (w2 * 12) * 32 + b;
                    const float* g1 = gph + l * 6144 + (w2 * 12) * 32 + b;
                    Dir += g0[(0 * 4 + j) * 32];
                    Diz += g0[(1 * 4 + j) * 32];
                    Dig += g0[(2 * 4 + j) * 32];
                    hr  += g1[(0 * 4 + j) * 32];
                    hz  += g1[(1 * 4 + j) * 32];
                    hg  += g1[(2 * 4 + j) * 32];
                }
                const float* bb = sbias + l * 24 + j * 6;
                float rm = rsv * mu;
                float ir = rsv * Dir - rm * sS[l * 12 + 0 * 4 + j] + sBc[l * 12 + 0 * 4 + j] + bb[0];
                float iz = rsv * Diz - rm * sS[l * 12 + 1 * 4 + j] + sBc[l * 12 + 1 * 4 + j] + bb[1];
                float ig = rsv * Dig - rm * sS[l * 12 + 2 * 4 + j] + sBc[l * 12 + 2 * 4 + j] + bb[2];
                hr += bb[3];
                hz += bb[4];
                hg += bb[5];

                float r = fsig(ir + hr);
                float z = fsig(iz + hz);
                float g = ftanh(ig + r * hg);
                float hprev = hTl[jg * 32 + b];
                float hn = (1.f - z) * g + z * hprev;
                hToutl[jg * 32 + b] = hn;
                float yv = xrT[jg * 32 + b] + alph[l] * hn;
                if (l == 0) {
                    g_xrbT[jg * 32 + b] = yv;
                } else {
                    g_ys_h[(size_t)(t * B_ + b) * 512 + jg] = __float2half_rn(yv);
                }
            }
            grid_bar(epoch);
        }
    }
}

// ============================ host orchestration ============================
extern "C" void kernel_launch(void* const* d_in, const int* in_sizes, int n_in,
                              void* d_out, int out_size)
{
    const int*   x    = (const int*)  d_in[0];
    const float* enc  = (const float*)d_in[1];
    const float* h0   = (const float*)d_in[2];
    const int*   vlen = (const int*)  d_in[3];
    const float* emb  = (const float*)d_in[4];
    const float* Wq   = (const float*)d_in[5];
    const float* Wk   = (const float*)d_in[6];
    const float* Wv   = (const float*)d_in[7];
    const float* Wo   = (const float*)d_in[8];
    const float* Win  = (const float*)d_in[9];
    const float* lng  = (const float*)d_in[10];
    const float* lnb  = (const float*)d_in[11];
    const float* alph = (const float*)d_in[12];
    const float* Wih  = (const float*)d_in[13];
    const float* Whh  = (const float*)d_in[14];
    const float* bih  = (const float*)d_in[15];
    const float* bhh  = (const float*)d_in[16];
    const float* Wd   = (const float*)d_in[17];
    const float* bd   = (const float*)d_in[18];
    float* out = (float*)d_out;

    cudaFuncSetAttribute(scan_kernel, cudaFuncAttributeMaxDynamicSharedMemorySize,
                         SCAN_SMEM_FLOATS * 4);
    cudaFuncSetAttribute(mma_gemm_kernel, cudaFuncAttributeMaxDynamicSharedMemorySize,
                         GEMM_DSM_BYTES);
    cudaFuncSetAttribute(mma_batched_kernel, cudaFuncAttributeMaxDynamicSharedMemorySize,
                         GEMM_DSM_BYTES);

    float *pKh, *pVh, *pEprojT, *pWcombT;
    __half *pEncH, *pWktH, *pWktL, *pWvtH, *pWvtL, *pWintH, *pWintL;
    __half *pWdtH, *pWdtL, *pEsH, *pEsL, *pYsH;
    cudaGetSymbolAddress((void**)&pKh,     g_Kh);
    cudaGetSymbolAddress((void**)&pVh,     g_Vh);
    cudaGetSymbolAddress((void**)&pEprojT, g_eprojT);
    cudaGetSymbolAddress((void**)&pWcombT, g_Wcombt);
    cudaGetSymbolAddress((void**)&pEncH,   g_enc_h);
    cudaGetSymbolAddress((void**)&pWktH,   g_Wkt_h);
    cudaGetSymbolAddress((void**)&pWktL,   g_Wkt_l);
    cudaGetSymbolAddress((void**)&pWvtH,   g_Wvt_h);
    cudaGetSymbolAddress((void**)&pWvtL,   g_Wvt_l);
    cudaGetSymbolAddress((void**)&pWintH,  g_Wint_h);
    cudaGetSymbolAddress((void**)&pWintL,  g_Wint_l);
    cudaGetSymbolAddress((void**)&pWdtH,   g_Wdt_h);
    cudaGetSymbolAddress((void**)&pWdtL,   g_Wdt_l);
    cudaGetSymbolAddress((void**)&pEsH,    g_eseq_h);
    cudaGetSymbolAddress((void**)&pEsL,    g_eseq_l);
    cudaGetSymbolAddress((void**)&pYsH,    g_ys_h);

    // launch 0: fused prep
    prep_all_kernel<<<PREP_BLOCKS, 256>>>(enc, Wk, Wv, Win, Wd, x, emb, h0);

    // launch 1: batched K/V (2-pass) + eprojT (3-pass) + Wcomb^T sgemm
    mma_batched_kernel<<<dim3(4, 64, 4), 256, GEMM_DSM_BYTES>>>(
        pEncH, pWktH, pWktL, pWvtH, pWvtL,
        pEsH, pEsL, pWintH, pWintL, pKh, pVh, pEprojT,
        Wo, Win, pWcombT);

    // launch 2: Kh transpose
    transpose_k_kernel<<<dim3(B_ * NH, TE / 32, DH / 32), dim3(32, 8)>>>();

    // launch 3: the whole 64-step scan (5 barriers, q-phase + hh overlap)
    scan_kernel<<<NBLK, NTHR, SCAN_SMEM_FLOATS * 4>>>(
        Wq, vlen, Wih, Whh, bih, bhh, lng, lnb, alph);

    // launch 4: logits (HMMA cp.async, fp16 2-pass), transposed write to (B,T,V)
    mma_gemm_kernel<<<dim3(V_ / 128, (TD * B_) / 128), 256, GEMM_DSM_BYTES>>>(
        TD * B_, V_, H_, pYsH, nullptr, pWdtH, pWdtL, out, bd, 1, 2);

    // launch 5: final hidden state (t=63 odd -> final state in g_hAT)
    if (out_size >= BTV + LBH)
        hfinal_kernel<<<(LBH + 255) / 256, 256>>>(out + BTV);
}

// round 16
// speedup vs baseline: 1.0226x; 1.0226x over previous
#include <cuda_runtime.h>
#include <cuda_fp16.h>
#include <math.h>
#include <stdint.h>

constexpr int B_  = 32;
constexpr int TD  = 64;
constexpr int TE  = 256;
constexpr int H_  = 512;
constexpr int E_  = 512;
constexpr int V_  = 32000;
constexpr int L_  = 2;
constexpr int NH  = 8;
constexpr int DH  = 64;
constexpr int BTV = B_ * TD * V_;
constexpr int LBH = L_ * B_ * H_;

constexpr int NBLK = 128;
constexpr int NTHR = 512;

// ---------------- scratch (device globals) ----------------------------------
__device__ __align__(16) float g_Kh  [B_ * TE * H_];
__device__ __align__(16) float g_Kh2 [B_ * NH * DH * TE];
__device__ __align__(16) float g_Vh  [B_ * TE * H_];
__device__ __align__(16) float g_eprojT[TD * H_ * B_];   // [t][k][b]
__device__ __align__(16) float g_Wcombt[H_ * H_];
__device__ __align__(16) float g_hA [B_ * H_];           // layer1 row (attention)
__device__ __align__(16) float g_hB [B_ * H_];
__device__ __align__(16) float g_hAT[L_ * H_ * B_];      // [l][k][b]
__device__ __align__(16) float g_hBT[L_ * H_ * B_];
__device__ __align__(16) float g_ctxT[H_ * B_];
__device__ __align__(16) float g_xraT[H_ * B_];
__device__ __align__(16) float g_xrbT[H_ * B_];
__device__ int g_bar;

__device__ __align__(16) __half g_enc_h [B_ * TE * 2 * H_];
__device__ __align__(16) __half g_Wkt_h [H_ * 2 * H_];
__device__ __align__(16) __half g_Wkt_l [H_ * 2 * H_];
__device__ __align__(16) __half g_Wvt_h [H_ * 2 * H_];
__device__ __align__(16) __half g_Wvt_l [H_ * 2 * H_];
__device__ __align__(16) __half g_Wint_h[H_ * H_];
__device__ __align__(16) __half g_Wint_l[H_ * H_];
__device__ __align__(16) __half g_Wdt_h [V_ * H_];
__device__ __align__(16) __half g_Wdt_l [V_ * H_];
__device__ __align__(16) __half g_eseq_h[TD * B_ * E_];
__device__ __align__(16) __half g_eseq_l[TD * B_ * E_];
__device__ __align__(16) __half g_ys_h  [TD * B_ * H_];

// ======================= helpers =============================================
__device__ __forceinline__ uint32_t smem_u32(const void* p) {
    uint32_t a;
    asm("{ .reg .u64 t; cvta.to.shared.u64 t, %1; cvt.u32.u64 %0, t; }"
        : "=r"(a) : "l"(p));
    return a;
}
__device__ __forceinline__ void ldsm4(uint32_t (&r)[4], uint32_t addr) {
    asm volatile("ldmatrix.sync.aligned.m8n8.x4.shared.b16 {%0,%1,%2,%3}, [%4];"
        : "=r"(r[0]), "=r"(r[1]), "=r"(r[2]), "=r"(r[3]) : "r"(addr));
}
__device__ __forceinline__ void mma16816(float (&d)[4], const uint32_t (&a)[4],
                                         uint32_t b0, uint32_t b1) {
    asm volatile(
        "mma.sync.aligned.m16n8k16.row.col.f32.f16.f16.f32 "
        "{%0,%1,%2,%3}, {%4,%5,%6,%7}, {%8,%9}, {%0,%1,%2,%3};"
        : "+f"(d[0]), "+f"(d[1]), "+f"(d[2]), "+f"(d[3])
        : "r"(a[0]), "r"(a[1]), "r"(a[2]), "r"(a[3]), "r"(b0), "r"(b1));
}
#define CPA16(dst, src) \
    asm volatile("cp.async.cg.shared.global [%0], [%1], 16;" \
                 :: "r"(dst), "l"(src) : "memory")
#define CP_COMMIT() asm volatile("cp.async.commit_group;" ::: "memory")
#define CP_WAIT1()  asm volatile("cp.async.wait_group 1;" ::: "memory")
#define CP_WAIT0()  asm volatile("cp.async.wait_group 0;" ::: "memory")

__device__ __forceinline__ float fsig(float x) {
    return 1.f / (1.f + __expf(-x));
}
__device__ __forceinline__ float ftanh(float x) {
    return 2.f / (1.f + __expf(-2.f * x)) - 1.f;
}
__device__ __forceinline__ void hsplit(float x, __half& h, __half& l) {
    h = __float2half_rn(x);
    l = __float2half_rn(x - __half2float(h));
}

// ============ HMMA compensated-fp16 GEMM (cp.async 2-stage pipeline) =========
// passes==3: D = Ah*Bh + Ah*Bl + Al*Bh ; passes==2: D = Ah*Bh + Ah*Bl
constexpr int BKg  = 32;
constexpr int LDSg = BKg + 8;
constexpr int GMSZ = 128 * LDSg;
constexpr int GSSZ = 4 * GMSZ;
constexpr int GEMM_DSM_BYTES = 2 * GSSZ * 2;

__device__ __forceinline__ void mma_gemm_body(
    char* dsm,
    int M, int N, int K,
    const __half* __restrict__ Ah, const __half* __restrict__ Al,
    const __half* __restrict__ Bh, const __half* __restrict__ Bl,
    float* __restrict__ C, const float* __restrict__ bias, int mode,
    int bx, int by, int passes)
{
    __half* sb = (__half*)dsm;
    const uint32_t sbase = smem_u32(sb);

    const int tid = threadIdx.x, lane = tid & 31, wid = tid >> 5;
    const int wm = wid >> 1, wn = wid & 1;
    const int n0 = bx * 128, m0 = by * 128;

    float acc[2][8][4];
#pragma unroll
    for (int i = 0; i < 2; i++)
#pragma unroll
        for (int j = 0; j < 8; j++)
#pragma unroll
            for (int k = 0; k < 4; k++) acc[i][j][k] = 0.f;

    const int lrow = tid >> 2;
    const int lcol = (tid & 3) * 8;
    const int nch = K >> 5;

    auto issue = [&](int kc, int st) {
        const int kb = kc << 5;
#pragma unroll
        for (int h = 0; h < 2; h++) {
            int row = lrow + h * 64;
            const __half* pa = Ah + (size_t)(m0 + row) * K + kb + lcol;
            const __half* pb = Bh + (size_t)(n0 + row) * K + kb + lcol;
            const __half* pq = Bl + (size_t)(n0 + row) * K + kb + lcol;
            uint32_t d = sbase + (uint32_t)(st * GSSZ + row * LDSg + lcol) * 2;
            CPA16(d,                pa);
            CPA16(d + 2 * GMSZ * 2, pb);
            CPA16(d + 3 * GMSZ * 2, pq);
            if (passes == 3) {
                const __half* pl = Al + (size_t)(m0 + row) * K + kb + lcol;
                CPA16(d + GMSZ * 2, pl);
            }
        }
        CP_COMMIT();
    };

    issue(0, 0);
    for (int kc = 0; kc < nch; kc++) {
        const int st = kc & 1;
        if (kc + 1 < nch) {
            issue(kc + 1, st ^ 1);
            CP_WAIT1();
        } else {
            CP_WAIT0();
        }
        __syncthreads();
        __half* sAh = sb + st * GSSZ;
        __half* sAl = sAh + GMSZ;
        __half* sBh = sAh + 2 * GMSZ;
        __half* sBl = sAh + 3 * GMSZ;

#pragma unroll
        for (int ks = 0; ks < BKg; ks += 16) {
            uint32_t ah[2][4], al[2][4];
            const uint32_t fcol = ks + (lane >> 4) * 8;
#pragma unroll
            for (int mi = 0; mi < 2; mi++) {
                uint32_t arow = wm * 32 + mi * 16 + (lane & 15);
                ldsm4(ah[mi], smem_u32(&sAh[arow * LDSg + fcol]));
                if (passes == 3)
                    ldsm4(al[mi], smem_u32(&sAl[arow * LDSg + fcol]));
            }
#pragma unroll
            for (int nj = 0; nj < 4; nj++) {
                uint32_t brow = wn * 64 + nj * 16 + (lane & 15);
                uint32_t bh[4], bl[4];
                ldsm4(bh, smem_u32(&sBh[brow * LDSg + fcol]));
                ldsm4(bl, smem_u32(&sBl[brow * LDSg + fcol]));
#pragma unroll
                for (int mi = 0; mi < 2; mi++) {
                    mma16816(acc[mi][2 * nj],     ah[mi], bh[0], bh[2]);
                    mma16816(acc[mi][2 * nj + 1], ah[mi], bh[1], bh[3]);
                    mma16816(acc[mi][2 * nj],     ah[mi], bl[0], bl[2]);
                    mma16816(acc[mi][2 * nj + 1], ah[mi], bl[1], bl[3]);
                    if (passes == 3) {
                        mma16816(acc[mi][2 * nj],     al[mi], bh[0], bh[2]);
                        mma16816(acc[mi][2 * nj + 1], al[mi], bh[1], bh[3]);
                    }
                }
            }
        }
        __syncthreads();
    }

#pragma unroll
    for (int mi = 0; mi < 2; mi++) {
        int row = m0 + wm * 32 + mi * 16 + (lane >> 2);
#pragma unroll
        for (int nt = 0; nt < 8; nt++) {
            int col = n0 + wn * 64 + nt * 8 + (lane & 3) * 2;
            float bb0 = bias ? bias[col] : 0.f;
            float bb1 = bias ? bias[col + 1] : 0.f;
            float2 v0 = make_float2(acc[mi][nt][0] + bb0, acc[mi][nt][1] + bb1);
            float2 v1 = make_float2(acc[mi][nt][2] + bb0, acc[mi][nt][3] + bb1);
            if (mode == 0) {
                *(float2*)&C[(size_t)row * N + col] = v0;
                *(float2*)&C[(size_t)(row + 8) * N + col] = v1;
            } else if (mode == 1) {
                int t0 = row >> 5, b0v_ = row & 31;
                int t1 = (row + 8) >> 5, b1v_ = (row + 8) & 31;
                *(float2*)&C[(size_t)b0v_ * (TD * V_) + (size_t)t0 * V_ + col] = v0;
                *(float2*)&C[(size_t)b1v_ * (TD * V_) + (size_t)t1 * V_ + col] = v1;
            } else {  // mode 2: eprojT[(t*512 + col)*32 + b]
                int t0 = row >> 5, b0v_ = row & 31;
                int t1 = (row + 8) >> 5, b1v_ = (row + 8) & 31;
                C[((size_t)t0 * 512 + col)     * 32 + b0v_] = v0.x;
                C[((size_t)t0 * 512 + col + 1) * 32 + b0v_] = v0.y;
                C[((size_t)t1 * 512 + col)     * 32 + b1v_] = v1.x;
                C[((size_t)t1 * 512 + col + 1) * 32 + b1v_] = v1.y;
            }
        }
    }
}

__global__ __launch_bounds__(256, 2) void mma_gemm_kernel(
    int M, int N, int K,
    const __half* __restrict__ Ah, const __half* __restrict__ Al,
    const __half* __restrict__ Bh, const __half* __restrict__ Bl,
    float* __restrict__ C, const float* __restrict__ bias, int mode, int passes)
{
    extern __shared__ __align__(16) char dsm[];
    mma_gemm_body(dsm, M, N, K, Ah, Al, Bh, Bl, C, bias, mode,
                  blockIdx.x, blockIdx.y, passes);
}

// fp32 SIMT GEMM body (512x512x512, transposed write) for Wcomb^T
__device__ void sgemm_tr_body(float* As, float* Bs,
    const float* __restrict__ A, const float* __restrict__ B,
    float* __restrict__ C, int bx, int by)
{
    const int tid = threadIdx.x;
    const float* Aptr = A + (size_t)(by * 128 + (tid >> 1)) * 512 + (tid & 1) * 4;
    const float* Bptr = B + (size_t)(tid >> 5) * 512 + bx * 128 + (tid & 31) * 4;
    const int ty = tid >> 4, tx = tid & 15;
    float acc[8][8];
#pragma unroll
    for (int i = 0; i < 8; i++)
#pragma unroll
        for (int j = 0; j < 8; j++) acc[i][j] = 0.f;
    for (int k0 = 0; k0 < 512; k0 += 8) {
        float4 av = *(const float4*)(Aptr + k0);
        float4 bv = *(const float4*)(Bptr + (size_t)k0 * 512);
        __syncthreads();
        const int ar_ = tid >> 1, ac_ = (tid & 1) * 4;
        As[(ac_ + 0) * 132 + ar_] = av.x; As[(ac_ + 1) * 132 + ar_] = av.y;
        As[(ac_ + 2) * 132 + ar_] = av.z; As[(ac_ + 3) * 132 + ar_] = av.w;
        *(float4*)&Bs[(tid >> 5) * 132 + (tid & 31) * 4] = bv;
        __syncthreads();
#pragma unroll
        for (int kk = 0; kk < 8; kk++) {
            float ar[8], br[8];
            *(float4*)(ar)     = *(float4*)&As[kk * 132 + ty * 4];
            *(float4*)(ar + 4) = *(float4*)&As[kk * 132 + ty * 4 + 64];
            *(float4*)(br)     = *(float4*)&Bs[kk * 132 + tx * 4];
            *(float4*)(br + 4) = *(float4*)&Bs[kk * 132 + tx * 4 + 64];
#pragma unroll
            for (int i = 0; i < 8; i++)
#pragma unroll
                for (int j = 0; j < 8; j++) acc[i][j] += ar[i] * br[j];
        }
    }
#pragma unroll
    for (int i = 0; i < 8; i++) {
        int m = by * 128 + ty * 4 + (i & 3) + (i >> 2) * 64;
#pragma unroll
        for (int j = 0; j < 8; j++) {
            int n = bx * 128 + tx * 4 + (j & 3) + (j >> 2) * 64;
            C[(size_t)n * 512 + m] = acc[i][j];
        }
    }
}

__global__ __launch_bounds__(256, 2) void mma_batched_kernel(
    const __half* __restrict__ encH,
    const __half* __restrict__ WkH,  const __half* __restrict__ WkL,
    const __half* __restrict__ WvH,  const __half* __restrict__ WvL,
    const __half* __restrict__ esH,  const __half* __restrict__ esL,
    const __half* __restrict__ WinH, const __half* __restrict__ WinL,
    float* __restrict__ Kh, float* __restrict__ Vh, float* __restrict__ eprojT,
    const float* __restrict__ Wo, const float* __restrict__ Win,
    float* __restrict__ WcombT)
{
    extern __shared__ __align__(16) char dsm[];
    int z = blockIdx.z;
    if (z == 0) {
        mma_gemm_body(dsm, B_ * TE, H_, 2 * H_,
                      encH, nullptr, WkH, WkL, Kh, nullptr, 0, blockIdx.x, blockIdx.y, 2);
    } else if (z == 1) {
        mma_gemm_body(dsm, B_ * TE, H_, 2 * H_,
                      encH, nullptr, WvH, WvL, Vh, nullptr, 0, blockIdx.x, blockIdx.y, 2);
    } else if (z == 2) {
        if (blockIdx.y >= (TD * B_) / 128) return;
        mma_gemm_body(dsm, TD * B_, H_, E_,
                      esH, esL, WinH, WinL, eprojT, nullptr, 2, blockIdx.x, blockIdx.y, 3);
    } else {
        if (blockIdx.x >= 4 || blockIdx.y >= 4) return;
        sgemm_tr_body((float*)dsm, (float*)dsm + 1056, Wo, Win, WcombT,
                      blockIdx.x, blockIdx.y);
    }
}

// ---------------- fused prep -------------------------------------------------
__device__ void tconv_body(const float* __restrict__ W, int K, int N, int row_off,
                           __half* __restrict__ oh, __half* __restrict__ ol,
                           int bxx, int byy, float* t)
{
    int tx = threadIdx.x & 31, ty = threadIdx.x >> 5;
    int n0 = bxx * 32, k0 = byy * 32;
    for (int ky = ty; ky < 32; ky += 8)
        t[ky * 33 + tx] = W[(size_t)(row_off + k0 + ky) * N + n0 + tx];
    __syncthreads();
    for (int ny = ty; ny < 32; ny += 8) {
        float v = t[tx * 33 + ny];
        __half h, l; hsplit(v, h, l);
        size_t o = (size_t)(n0 + ny) * K + k0 + tx;
        oh[o] = h; ol[o] = l;
    }
}

constexpr int SEG0 = (B_ * TE * 2 * H_) / 4 / 256;   // 8192
constexpr int SEG1 = SEG0 + 512;
constexpr int SEG2 = SEG1 + 512;
constexpr int SEG3 = SEG2 + 256;
constexpr int SEG4 = SEG3 + 16000;
constexpr int SEG5 = SEG4 + 2048;
constexpr int SEG6 = SEG5 + 128;
constexpr int PREP_BLOCKS = SEG6;

__global__ __launch_bounds__(256) void prep_all_kernel(
    const float* __restrict__ enc, const float* __restrict__ Wk,
    const float* __restrict__ Wv, const float* __restrict__ Win,
    const float* __restrict__ Wd, const int* __restrict__ x,
    const float* __restrict__ emb, const float* __restrict__ h0)
{
    __shared__ float t[32 * 33];
    int blk = blockIdx.x, tid = threadIdx.x;
    if (blk == 0 && tid == 0) g_bar = 0;
    if (blk < SEG0) {
        int i = blk * 256 + tid;
        float4 v = ((const float4*)enc)[i];
        ((__half2*)g_enc_h)[2 * i]     = __half2(__float2half_rn(v.x), __float2half_rn(v.y));
        ((__half2*)g_enc_h)[2 * i + 1] = __half2(__float2half_rn(v.z), __float2half_rn(v.w));
    } else if (blk < SEG1) {
        int i = blk - SEG0;
        tconv_body(Wk, 2 * H_, H_, 0, g_Wkt_h, g_Wkt_l, i % 16, i / 16, t);
    } else if (blk < SEG2) {
        int i = blk - SEG1;
        tconv_body(Wv, 2 * H_, H_, 0, g_Wvt_h, g_Wvt_l, i % 16, i / 16, t);
    } else if (blk < SEG3) {
        int i = blk - SEG2;
        tconv_body(Win, H_, H_, 512, g_Wint_h, g_Wint_l, i % 16, i / 16, t);
    } else if (blk < SEG4) {
        int i = blk - SEG3;
        tconv_body(Wd, H_, V_, 0, g_Wdt_h, g_Wdt_l, i % 1000, i / 1000, t);
    } else if (blk < SEG5) {
        int r = blk - SEG4;
        int tt = r >> 5, b = r & 31;
        int tok = x[b * TD + tt];
        const float* src = emb + (size_t)tok * E_;
        for (int i = tid; i < E_; i += 256) {
            __half h, l; hsplit(src[i], h, l);
            g_eseq_h[(size_t)r * E_ + i] = h;
            g_eseq_l[(size_t)r * E_ + i] = l;
        }
    } else {
        int i = (blk - SEG5) * 256 + tid;     // 0..32767 over [l][b][k]
        int l = i >> 14, b = (i >> 9) & 31, k = i & 511;
        float v = h0[i];
        g_hAT[((size_t)l * 512 + k) * 32 + b] = v;
        if (l == 1) g_hA[b * 512 + k] = v;
    }
}

// ---------------- transpose Kh (b,s,h,d) -> Kh2 (b,h,d,s) --------------------
__global__ void transpose_k_kernel()
{
    __shared__ float t[32][33];
    int bh = blockIdx.x;
    int b = bh >> 3, h = bh & 7;
    int s0 = blockIdx.y * 32, d0 = blockIdx.z * 32;
    for (int yy = threadIdx.y; yy < 32; yy += 8)
        t[yy][threadIdx.x] = g_Kh[((size_t)(b * 256 + s0 + yy) * 8 + h) * 64 + d0 + threadIdx.x];
    __syncthreads();
    for (int yy = threadIdx.y; yy < 32; yy += 8)
        g_Kh2[((size_t)(bh) * 64 + d0 + yy) * 256 + s0 + threadIdx.x] = t[threadIdx.x][yy];
}

__global__ void hfinal_kernel(float* __restrict__ dst)
{
    int i = blockIdx.x * blockDim.x + threadIdx.x;
    if (i < LBH) {
        int l = i >> 14, b = (i >> 9) & 31, k = i & 511;
        dst[i] = g_hAT[((size_t)l * 512 + k) * 32 + b];
    }
}

// =================== PERSISTENT SCAN KERNEL (R14 + vlen V bound) =============
constexpr int OFF_W   = 0;        // 24576: w[l][k][24] (ih gamma-folded)
constexpr int OFF_WC  = 24576;    // 2048:  Wcomb slice [k][4j]
constexpr int OFF_GP  = 26624;    // 6144:  ih/xr partials; attention alias (2x1088)
constexpr int OFF_HH  = 32768;    // 12288: hh partials [l][6144]
constexpr int OFF_GS  = 45056;    // 1024:  stats partials
constexpr int OFF_S   = 46080;    // 24
constexpr int OFF_BC  = 46104;    // 24
constexpr int OFF_SB  = 46128;    // 48
constexpr int SCAN_SMEM_FLOATS = 46208;   // 184832 B

__device__ __forceinline__ void bar_arrive(int& epoch) {
    __syncthreads();
    epoch += NBLK;
    if (threadIdx.x == 0) {
        int* p = &g_bar;
        asm volatile("red.release.gpu.global.add.s32 [%0], 1;" :: "l"(p) : "memory");
    }
}
__device__ __forceinline__ void bar_wait(int epoch) {
    if (threadIdx.x == 0) {
        int* p = &g_bar;
        int v;
        do {
            asm volatile("ld.acquire.gpu.global.s32 %0, [%1];" : "=r"(v) : "l"(p) : "memory");
        } while (v < epoch);
    }
    __syncthreads();
}
__device__ __forceinline__ void grid_bar(int& epoch) {
    bar_arrive(epoch);
    bar_wait(epoch);
}

__global__ __launch_bounds__(NTHR, 1) void scan_kernel(
    const float* __restrict__ Wq,  const int* __restrict__ vlen,
    const float* __restrict__ Wih, const float* __restrict__ Whh,
    const float* __restrict__ bih, const float* __restrict__ bhh,
    const float* __restrict__ lng, const float* __restrict__ lnb,
    const float* __restrict__ alph)
{
    extern __shared__ float sm[];
    float* w    = sm + OFF_W;
    float* wcs  = sm + OFF_WC;
    float* gp   = sm + OFF_GP;
    float* at   = sm + OFF_GP;
    float* gph  = sm + OFF_HH;
    float* gs1  = sm + OFF_GS;
    float* gs2  = sm + OFF_GS + 512;
    float* sS   = sm + OFF_S;
    float* sBc  = sm + OFF_BC;
    float* sbias = sm + OFF_SB;

    const int tid = threadIdx.x, lane = tid & 31, wid = tid >> 5;
    const int blk = blockIdx.x;
    int epoch = 0;

    // ---- one-time weight staging (raw) ----
    for (int i = tid; i < 24576; i += NTHR) {
        int unit = i >> 9, k = i & 511;
        int l = unit / 24, idx = unit % 24;
        int pass = idx / 12, r = idx % 12;
        int g = r >> 2, j = r & 3;
        const float* src = (pass == 0)
            ? (Wih + ((size_t)l * 1536 + g * 512 + blk * 4 + j) * 512)
            : (Whh + ((size_t)l * 1536 + g * 512 + blk * 4 + j) * 512);
        w[((l * 512 + k) * 24) + pass * 12 + g * 4 + j] = src[k];
    }
    for (int i = tid; i < 2048; i += NTHR) {
        int k = i >> 2, j = i & 3;
        wcs[i] = g_Wcombt[(size_t)(blk * 4 + j) * 512 + k];
    }
    if (tid < 48) {
        int l = tid / 24, r = tid % 24;
        int j = r / 6, g6 = r % 6;
        int jg = blk * 4 + j;
        sbias[tid] = (g6 < 3) ? bih[l * 1536 + g6 * 512 + jg]
                              : bhh[l * 1536 + (g6 - 3) * 512 + jg];
    }
    __syncthreads();
    if (tid < 24) {
        int l = tid / 12, idx = tid % 12;
        float s = 0.f, bc = 0.f;
        for (int k = 0; k < 512; k++) {
            float rw = w[((l * 512 + k) * 24) + idx];
            s  += lng[l * 512 + k] * rw;
            bc += lnb[l * 512 + k] * rw;
        }
        sS[tid] = s;
        sBc[tid] = bc;
    }
    __syncthreads();
    for (int i = tid; i < 12288; i += NTHR) {
        int l = i / 6144, r = i % 6144;
        int k = r / 12, idx = r % 12;
        w[((l * 512 + k) * 24) + idx] *= lng[l * 512 + k];
    }
    __syncthreads();

    for (int t = 0; t < TD; t++) {
        const float* hinRow = (t & 1) ? g_hB : g_hA;
        float*       houtRow = (t & 1) ? g_hA : g_hB;
        const float* hinT  = (t & 1) ? g_hBT : g_hAT;
        float*       houtT = (t & 1) ? g_hAT : g_hBT;

        // ================= phase 1: attention ================================
        {
            int grp = tid >> 8, lt = tid & 255;
            int u = blk * 2 + grp;
            int b = u >> 3, h = u & 7;
            float* sh_ = at + grp * 1088;
            float* sq_ = sh_ + 512;
            float* sp_ = sq_ + 64;
            float* rd_ = sp_ + 256;
            const float* hlast = hinRow + b * 512;

            sh_[lt] = hlast[lt];
            sh_[lt + 256] = hlast[lt + 256];
            __syncthreads();

            int d = lt & 63, c = lt >> 6;
            {
                float a0 = 0.f, a1 = 0.f;
                const float* wq = Wq + h * 64 + d;
#pragma unroll 8
                for (int k = c * 128; k < c * 128 + 128; k += 2) {
                    a0 += sh_[k]     * wq[(size_t)k * 512];
                    a1 += sh_[k + 1] * wq[(size_t)(k + 1) * 512];
                }
                rd_[lt] = a0 + a1;
            }
            __syncthreads();
            if (lt < 64) sq_[lt] = rd_[lt] + rd_[lt + 64] + rd_[lt + 128] + rd_[lt + 192];
            __syncthreads();

            float sc = -1e6f;
            int vl = vlen[b];
            if (lt < vl) {
                float a0 = 0.f, a1 = 0.f;
                const float* kp = g_Kh2 + (size_t)u * 64 * 256 + lt;
#pragma unroll 8
                for (int dd = 0; dd < 64; dd += 2) {
                    a0 += sq_[dd]     * kp[dd * 256];
                    a1 += sq_[dd + 1] * kp[(dd + 1) * 256];
                }
                sc = (a0 + a1) * 0.125f;
            }
            int wg = lt >> 5;
            float m = sc;
#pragma unroll
            for (int o = 16; o; o >>= 1) m = fmaxf(m, __shfl_xor_sync(0xffffffffu, m, o));
            if ((lt & 31) == 0) rd_[wg] = m;
            __syncthreads();
            float mx = rd_[0];
#pragma unroll
            for (int i = 1; i < 8; i++) mx = fmaxf(mx, rd_[i]);
            float p = __expf(sc - mx);
            float s = p;
#pragma unroll
            for (int o = 16; o; o >>= 1) s += __shfl_xor_sync(0xffffffffu, s, o);
            if ((lt & 31) == 0) rd_[8 + wg] = s;
            __syncthreads();
            float sum = rd_[8];
#pragma unroll
            for (int i = 1; i < 8; i++) sum += rd_[8 + i];
            sp_[lt] = p / sum;
            __syncthreads();

            {
                // skip s >= vlen: those sp_ are exactly 0 (exp underflow)
                int lim = vl - c * 64;
                if (lim > 64) lim = 64;
                float a0 = 0.f, a1 = 0.f;
                const float* vp = g_Vh + ((size_t)(b * 256 + c * 64) * 8 + h) * 64 + d;
                int ss = 0;
#pragma unroll 4
                for (; ss + 1 < lim; ss += 2) {
                    a0 += sp_[c * 64 + ss]     * vp[(size_t)ss * 512];
                    a1 += sp_[c * 64 + ss + 1] * vp[(size_t)(ss + 1) * 512];
                }
                if (ss < lim) a0 += sp_[c * 64 + ss] * vp[(size_t)ss * 512];
                rd_[lt] = a0 + a1;
            }
            __syncthreads();
            if (lt < 64)
                g_ctxT[(h * 64 + lt) * 32 + b] =
                    rd_[lt] + rd_[lt + 64] + rd_[lt + 128] + rd_[lt + 192];
        }
        bar_arrive(epoch);

        // ===== overlap window: hh matvecs for BOTH layers (depend on hinT) ==
        {
            const int kc = wid * 32;
#pragma unroll
            for (int l = 0; l < 2; l++) {
                const float* hTl = hinT + (size_t)l * 512 * 32;
                float acc[12];
#pragma unroll
                for (int i = 0; i < 12; i++) acc[i] = 0.f;
                const float* wrow = w + ((size_t)(l * 512 + kc) * 24) + 12;
#pragma unroll 8
                for (int kk = 0; kk < 32; kk++) {
                    float xv = hTl[(kc + kk) * 32 + lane];
                    float4 w0 = *(const float4*)(wrow + kk * 24 + 0);
                    float4 w1 = *(const float4*)(wrow + kk * 24 + 4);
                    float4 w2 = *(const float4*)(wrow + kk * 24 + 8);
                    acc[0] += w0.x * xv; acc[1] += w0.y * xv; acc[2] += w0.z * xv; acc[3] += w0.w * xv;
                    acc[4] += w1.x * xv; acc[5] += w1.y * xv; acc[6] += w1.z * xv; acc[7] += w1.w * xv;
                    acc[8] += w2.x * xv; acc[9] += w2.y * xv; acc[10] += w2.z * xv; acc[11] += w2.w * xv;
                }
#pragma unroll
                for (int i = 0; i < 12; i++)
                    gph[l * 6144 + (wid * 12 + i) * 32 + lane] = acc[i];
            }
        }
        bar_wait(epoch);

        // ================= phase 2: xr = ctx @ Wcomb + eprojT ===============
        {
            int kc = wid * 32;
            float a0 = 0.f, a1 = 0.f, a2 = 0.f, a3 = 0.f;
#pragma unroll 8
            for (int kk = 0; kk < 32; kk++) {
                int k = kc + kk;
                float xv = g_ctxT[k * 32 + lane];
                float4 wv = *(const float4*)(wcs + k * 4);
                a0 += wv.x * xv; a1 += wv.y * xv; a2 += wv.z * xv; a3 += wv.w * xv;
            }
            gp[(wid * 4 + 0) * 32 + lane] = a0;
            gp[(wid * 4 + 1) * 32 + lane] = a1;
            gp[(wid * 4 + 2) * 32 + lane] = a2;
            gp[(wid * 4 + 3) * 32 + lane] = a3;
        }
        __syncthreads();
        if (tid < 128) {
            int j = tid >> 5, b = tid & 31, jg = blk * 4 + j;
            float v = 0.f;
#pragma unroll
            for (int w2 = 0; w2 < 16; w2++) v += gp[(w2 * 4 + j) * 32 + b];
            v += g_eprojT[((size_t)t * 512 + jg) * 32 + b];
            g_xraT[jg * 32 + b] = v;
        }
        grid_bar(epoch);

        // ================= phases 3,4: GRU layers (ih + combine only) =======
        for (int l = 0; l < 2; l++) {
            const float* xrT = (l == 0) ? g_xraT : g_xrbT;
            const float* hTl = hinT + (size_t)l * 512 * 32;
            float* hToutl = houtT + (size_t)l * 512 * 32;

            const int kc = wid * 32;
            // ih pass (gamma-folded weights) + stats
            {
                float acc[12];
#pragma unroll
                for (int i = 0; i < 12; i++) acc[i] = 0.f;
                float s1 = 0.f, s2 = 0.f;
                const float* wrow = w + ((size_t)(l * 512 + kc) * 24);
#pragma unroll 8
                for (int kk = 0; kk < 32; kk++) {
                    float xv = xrT[(kc + kk) * 32 + lane];
                    s1 += xv; s2 += xv * xv;
                    float4 w0 = *(const float4*)(wrow + kk * 24 + 0);
                    float4 w1 = *(const float4*)(wrow + kk * 24 + 4);
                    float4 w2 = *(const float4*)(wrow + kk * 24 + 8);
                    acc[0] += w0.x * xv; acc[1] += w0.y * xv; acc[2] += w0.z * xv; acc[3] += w0.w * xv;
                    acc[4] += w1.x * xv; acc[5] += w1.y * xv; acc[6] += w1.z * xv; acc[7] += w1.w * xv;
                    acc[8] += w2.x * xv; acc[9] += w2.y * xv; acc[10] += w2.z * xv; acc[11] += w2.w * xv;
                }
#pragma unroll
                for (int i = 0; i < 12; i++)
                    gp[(wid * 12 + i) * 32 + lane] = acc[i];
                gs1[wid * 32 + lane] = s1;
                gs2[wid * 32 + lane] = s2;
            }
            __syncthreads();
            // combine (LN applied algebraically)
            if (tid < 128) {
                int j = tid >> 5, b = tid & 31, jg = blk * 4 + j;
                float s1 = 0.f, s2 = 0.f;
#pragma unroll
                for (int w2 = 0; w2 < 16; w2++) {
                    s1 += gs1[w2 * 32 + b];
                    s2 += gs2[w2 * 32 + b];
                }
                float mu = s1 * (1.f / 512.f);
                float var = s2 * (1.f / 512.f) - mu * mu;
                float rsv = rsqrtf(var + 1e-5f);

                float Dir = 0.f, Diz = 0.f, Dig = 0.f, hr = 0.f, hz = 0.f, hg = 0.f;
#pragma unroll
                for (int w2 = 0; w2 < 16; w2++) {
                    const float* g0 = gp + (w2 * 12) * 32 + b;
                    const float* g1 = gph + l * 6144 + (w2 * 12) * 32 + b;
                    Dir += g0[(0 * 4 + j) * 32];
                    Diz += g0[(1 * 4 + j) * 32];
                    Dig += g0[(2 * 4 + j) * 32];
                    hr  += g1[(0 * 4 + j) * 32];
                    hz  += g1[(1 * 4 + j) * 32];
                    hg  += g1[(2 * 4 + j) * 32];
                }
                const float* bb = sbias + l * 24 + j * 6;
                float rm = rsv * mu;
                float ir = rsv * Dir - rm * sS[l * 12 + 0 * 4 + j] + sBc[l * 12 + 0 * 4 + j] + bb[0];
                float iz = rsv * Diz - rm * sS[l * 12 + 1 * 4 + j] + sBc[l * 12 + 1 * 4 + j] + bb[1];
                float ig = rsv * Dig - rm * sS[l * 12 + 2 * 4 + j] + sBc[l * 12 + 2 * 4 + j] + bb[2];
                hr += bb[3];
                hz += bb[4];
                hg += bb[5];

                float r = fsig(ir + hr);
                float z = fsig(iz + hz);
                float g = ftanh(ig + r * hg);
                float hprev = hTl[jg * 32 + b];
                float hn = (1.f - z) * g + z * hprev;
                hToutl[jg * 32 + b] = hn;
                if (l == 1) houtRow[b * 512 + jg] = hn;
                float yv = xrT[jg * 32 + b] + alph[l] * hn;
                if (l == 0) {
                    g_xrbT[jg * 32 + b] = yv;
                } else {
                    g_ys_h[(size_t)(t * B_ + b) * 512 + jg] = __float2half_rn(yv);
                }
            }
            grid_bar(epoch);
        }
    }
}

// ============================ host orchestration ============================
extern "C" void kernel_launch(void* const* d_in, const int* in_sizes, int n_in,
                              void* d_out, int out_size)
{
    const int*   x    = (const int*)  d_in[0];
    const float* enc  = (const float*)d_in[1];
    const float* h0   = (const float*)d_in[2];
    const int*   vlen = (const int*)  d_in[3];
    const float* emb  = (const float*)d_in[4];
    const float* Wq   = (const float*)d_in[5];
    const float* Wk   = (const float*)d_in[6];
    const float* Wv   = (const float*)d_in[7];
    const float* Wo   = (const float*)d_in[8];
    const float* Win  = (const float*)d_in[9];
    const float* lng  = (const float*)d_in[10];
    const float* lnb  = (const float*)d_in[11];
    const float* alph = (const float*)d_in[12];
    const float* Wih  = (const float*)d_in[13];
    const float* Whh  = (const float*)d_in[14];
    const float* bih  = (const float*)d_in[15];
    const float* bhh  = (const float*)d_in[16];
    const float* Wd   = (const float*)d_in[17];
    const float* bd   = (const float*)d_in[18];
    float* out = (float*)d_out;

    cudaFuncSetAttribute(scan_kernel, cudaFuncAttributeMaxDynamicSharedMemorySize,
                         SCAN_SMEM_FLOATS * 4);
    cudaFuncSetAttribute(mma_gemm_kernel, cudaFuncAttributeMaxDynamicSharedMemorySize,
                         GEMM_DSM_BYTES);
    cudaFuncSetAttribute(mma_batched_kernel, cudaFuncAttributeMaxDynamicSharedMemorySize,
                         GEMM_DSM_BYTES);

    float *pKh, *pVh, *pEprojT, *pWcombT;
    __half *pEncH, *pWktH, *pWktL, *pWvtH, *pWvtL, *pWintH, *pWintL;
    __half *pWdtH, *pWdtL, *pEsH, *pEsL, *pYsH;
    cudaGetSymbolAddress((void**)&pKh,     g_Kh);
    cudaGetSymbolAddress((void**)&pVh,     g_Vh);
    cudaGetSymbolAddress((void**)&pEprojT, g_eprojT);
    cudaGetSymbolAddress((void**)&pWcombT, g_Wcombt);
    cudaGetSymbolAddress((void**)&pEncH,   g_enc_h);
    cudaGetSymbolAddress((void**)&pWktH,   g_Wkt_h);
    cudaGetSymbolAddress((void**)&pWktL,   g_Wkt_l);
    cudaGetSymbolAddress((void**)&pWvtH,   g_Wvt_h);
    cudaGetSymbolAddress((void**)&pWvtL,   g_Wvt_l);
    cudaGetSymbolAddress((void**)&pWintH,  g_Wint_h);
    cudaGetSymbolAddress((void**)&pWintL,  g_Wint_l);
    cudaGetSymbolAddress((void**)&pWdtH,   g_Wdt_h);
    cudaGetSymbolAddress((void**)&pWdtL,   g_Wdt_l);
    cudaGetSymbolAddress((void**)&pEsH,    g_eseq_h);
    cudaGetSymbolAddress((void**)&pEsL,    g_eseq_l);
    cudaGetSymbolAddress((void**)&pYsH,    g_ys_h);

    // launch 0: fused prep
    prep_all_kernel<<<PREP_BLOCKS, 256>>>(enc, Wk, Wv, Win, Wd, x, emb, h0);

    // launch 1: batched K/V (fp16 2-pass) + eprojT (3-pass) + Wcomb^T sgemm
    mma_batched_kernel<<<dim3(4, 64, 4), 256, GEMM_DSM_BYTES>>>(
        pEncH, pWktH, pWktL, pWvtH, pWvtL,
        pEsH, pEsL, pWintH, pWintL, pKh, pVh, pEprojT,
        Wo, Win, pWcombT);

    // launch 2: Kh transpose
    transpose_k_kernel<<<dim3(B_ * NH, TE / 32, DH / 32), dim3(32, 8)>>>();

    // launch 3: the whole 64-step scan (R14 structure + vlen-bounded V)
    scan_kernel<<<NBLK, NTHR, SCAN_SMEM_FLOATS * 4>>>(
        Wq, vlen, Wih, Whh, bih, bhh, lng, lnb, alph);

    // launch 4: logits (HMMA cp.async, fp16 2-pass), transposed write to (B,T,V)
    mma_gemm_kernel<<<dim3(V_ / 128, (TD * B_) / 128), 256, GEMM_DSM_BYTES>>>(
        TD * B_, V_, H_, pYsH, nullptr, pWdtH, pWdtL, out, bd, 1, 2);

    // launch 5: final hidden state (t=63 odd -> final state in g_hAT)
    if (out_size >= BTV + LBH)
        hfinal_kernel<<<(LBH + 255) / 256, 256>>>(out + BTV);
}

// round 17
// speedup vs baseline: 1.0635x; 1.0400x over previous
#include <cuda_runtime.h>
#include <cuda_fp16.h>
#include <math.h>
#include <stdint.h>

constexpr int B_  = 32;
constexpr int TD  = 64;
constexpr int TE  = 256;
constexpr int H_  = 512;
constexpr int E_  = 512;
constexpr int V_  = 32000;
constexpr int L_  = 2;
constexpr int NH  = 8;
constexpr int DH  = 64;
constexpr int BTV = B_ * TD * V_;
constexpr int LBH = L_ * B_ * H_;

constexpr int NBLK = 128;
constexpr int NTHR = 512;

// ---------------- scratch (device globals) ----------------------------------
__device__ __align__(16) float g_Kh  [B_ * TE * H_];
__device__ __align__(16) float g_Kh2 [B_ * NH * DH * TE];
__device__ __align__(16) float g_Vh  [B_ * TE * H_];
__device__ __align__(16) float g_eprojT[TD * H_ * B_];   // [t][k][b]
__device__ __align__(16) float g_Wcombt[H_ * H_];
__device__ __align__(16) float g_hA [B_ * H_];           // layer1 row (attention)
__device__ __align__(16) float g_hB [B_ * H_];
__device__ __align__(16) float g_hAT[L_ * H_ * B_];      // [l][k][b]
__device__ __align__(16) float g_hBT[L_ * H_ * B_];
__device__ __align__(16) float g_ctxT[H_ * B_];
__device__ __align__(16) float g_xraT[H_ * B_];
__device__ __align__(16) float g_xrbT[H_ * B_];
__device__ int g_bar;

__device__ __align__(16) __half g_enc_h [B_ * TE * 2 * H_];
__device__ __align__(16) __half g_Wkt_h [H_ * 2 * H_];
__device__ __align__(16) __half g_Wkt_l [H_ * 2 * H_];
__device__ __align__(16) __half g_Wvt_h [H_ * 2 * H_];
__device__ __align__(16) __half g_Wvt_l [H_ * 2 * H_];
__device__ __align__(16) __half g_Wint_h[H_ * H_];
__device__ __align__(16) __half g_Wint_l[H_ * H_];
__device__ __align__(16) __half g_Wdt_h [V_ * H_];
__device__ __align__(16) __half g_Wdt_l [V_ * H_];
__device__ __align__(16) __half g_eseq_h[TD * B_ * E_];
__device__ __align__(16) __half g_eseq_l[TD * B_ * E_];
__device__ __align__(16) __half g_ys_h  [TD * B_ * H_];

// ======================= helpers =============================================
__device__ __forceinline__ uint32_t smem_u32(const void* p) {
    uint32_t a;
    asm("{ .reg .u64 t; cvta.to.shared.u64 t, %1; cvt.u32.u64 %0, t; }"
        : "=r"(a) : "l"(p));
    return a;
}
__device__ __forceinline__ void ldsm4(uint32_t (&r)[4], uint32_t addr) {
    asm volatile("ldmatrix.sync.aligned.m8n8.x4.shared.b16 {%0,%1,%2,%3}, [%4];"
        : "=r"(r[0]), "=r"(r[1]), "=r"(r[2]), "=r"(r[3]) : "r"(addr));
}
__device__ __forceinline__ void mma16816(float (&d)[4], const uint32_t (&a)[4],
                                         uint32_t b0, uint32_t b1) {
    asm volatile(
        "mma.sync.aligned.m16n8k16.row.col.f32.f16.f16.f32 "
        "{%0,%1,%2,%3}, {%4,%5,%6,%7}, {%8,%9}, {%0,%1,%2,%3};"
        : "+f"(d[0]), "+f"(d[1]), "+f"(d[2]), "+f"(d[3])
        : "r"(a[0]), "r"(a[1]), "r"(a[2]), "r"(a[3]), "r"(b0), "r"(b1));
}
#define CPA16(dst, src) \
    asm volatile("cp.async.cg.shared.global [%0], [%1], 16;" \
                 :: "r"(dst), "l"(src) : "memory")
#define CP_COMMIT() asm volatile("cp.async.commit_group;" ::: "memory")
#define CP_WAIT1()  asm volatile("cp.async.wait_group 1;" ::: "memory")
#define CP_WAIT0()  asm volatile("cp.async.wait_group 0;" ::: "memory")

__device__ __forceinline__ float fsig(float x) {
    return 1.f / (1.f + __expf(-x));
}
__device__ __forceinline__ float ftanh(float x) {
    return 2.f / (1.f + __expf(-2.f * x)) - 1.f;
}
__device__ __forceinline__ void hsplit(float x, __half& h, __half& l) {
    h = __float2half_rn(x);
    l = __float2half_rn(x - __half2float(h));
}

// ============ HMMA compensated-fp16 GEMM (cp.async 2-stage pipeline) =========
// passes==3: D = Ah*Bh + Ah*Bl + Al*Bh ; passes==2: D = Ah*Bh + Ah*Bl
constexpr int BKg  = 32;
constexpr int LDSg = BKg + 8;
constexpr int GMSZ = 128 * LDSg;
constexpr int GSSZ = 4 * GMSZ;
constexpr int GEMM_DSM_BYTES = 2 * GSSZ * 2;

__device__ __forceinline__ void mma_gemm_body(
    char* dsm,
    int M, int N, int K,
    const __half* __restrict__ Ah, const __half* __restrict__ Al,
    const __half* __restrict__ Bh, const __half* __restrict__ Bl,
    float* __restrict__ C, const float* __restrict__ bias, int mode,
    int bx, int by, int passes)
{
    __half* sb = (__half*)dsm;
    const uint32_t sbase = smem_u32(sb);

    const int tid = threadIdx.x, lane = tid & 31, wid = tid >> 5;
    const int wm = wid >> 1, wn = wid & 1;
    const int n0 = bx * 128, m0 = by * 128;

    float acc[2][8][4];
#pragma unroll
    for (int i = 0; i < 2; i++)
#pragma unroll
        for (int j = 0; j < 8; j++)
#pragma unroll
            for (int k = 0; k < 4; k++) acc[i][j][k] = 0.f;

    const int lrow = tid >> 2;
    const int lcol = (tid & 3) * 8;
    const int nch = K >> 5;

    auto issue = [&](int kc, int st) {
        const int kb = kc << 5;
#pragma unroll
        for (int h = 0; h < 2; h++) {
            int row = lrow + h * 64;
            const __half* pa = Ah + (size_t)(m0 + row) * K + kb + lcol;
            const __half* pb = Bh + (size_t)(n0 + row) * K + kb + lcol;
            const __half* pq = Bl + (size_t)(n0 + row) * K + kb + lcol;
            uint32_t d = sbase + (uint32_t)(st * GSSZ + row * LDSg + lcol) * 2;
            CPA16(d,                pa);
            CPA16(d + 2 * GMSZ * 2, pb);
            CPA16(d + 3 * GMSZ * 2, pq);
            if (passes == 3) {
                const __half* pl = Al + (size_t)(m0 + row) * K + kb + lcol;
                CPA16(d + GMSZ * 2, pl);
            }
        }
        CP_COMMIT();
    };

    issue(0, 0);
    for (int kc = 0; kc < nch; kc++) {
        const int st = kc & 1;
        if (kc + 1 < nch) {
            issue(kc + 1, st ^ 1);
            CP_WAIT1();
        } else {
            CP_WAIT0();
        }
        __syncthreads();
        __half* sAh = sb + st * GSSZ;
        __half* sAl = sAh + GMSZ;
        __half* sBh = sAh + 2 * GMSZ;
        __half* sBl = sAh + 3 * GMSZ;

#pragma unroll
        for (int ks = 0; ks < BKg; ks += 16) {
            uint32_t ah[2][4], al[2][4];
            const uint32_t fcol = ks + (lane >> 4) * 8;
#pragma unroll
            for (int mi = 0; mi < 2; mi++) {
                uint32_t arow = wm * 32 + mi * 16 + (lane & 15);
                ldsm4(ah[mi], smem_u32(&sAh[arow * LDSg + fcol]));
                if (passes == 3)
                    ldsm4(al[mi], smem_u32(&sAl[arow * LDSg + fcol]));
            }
#pragma unroll
            for (int nj = 0; nj < 4; nj++) {
                uint32_t brow = wn * 64 + nj * 16 + (lane & 15);
                uint32_t bh[4], bl[4];
                ldsm4(bh, smem_u32(&sBh[brow * LDSg + fcol]));
                ldsm4(bl, smem_u32(&sBl[brow * LDSg + fcol]));
#pragma unroll
                for (int mi = 0; mi < 2; mi++) {
                    mma16816(acc[mi][2 * nj],     ah[mi], bh[0], bh[2]);
                    mma16816(acc[mi][2 * nj + 1], ah[mi], bh[1], bh[3]);
                    mma16816(acc[mi][2 * nj],     ah[mi], bl[0], bl[2]);
                    mma16816(acc[mi][2 * nj + 1], ah[mi], bl[1], bl[3]);
                    if (passes == 3) {
                        mma16816(acc[mi][2 * nj],     al[mi], bh[0], bh[2]);
                        mma16816(acc[mi][2 * nj + 1], al[mi], bh[1], bh[3]);
                    }
                }
            }
        }
        __syncthreads();
    }

#pragma unroll
    for (int mi = 0; mi < 2; mi++) {
        int row = m0 + wm * 32 + mi * 16 + (lane >> 2);
#pragma unroll
        for (int nt = 0; nt < 8; nt++) {
            int col = n0 + wn * 64 + nt * 8 + (lane & 3) * 2;
            float bb0 = bias ? bias[col] : 0.f;
            float bb1 = bias ? bias[col + 1] : 0.f;
            float2 v0 = make_float2(acc[mi][nt][0] + bb0, acc[mi][nt][1] + bb1);
            float2 v1 = make_float2(acc[mi][nt][2] + bb0, acc[mi][nt][3] + bb1);
            if (mode == 0) {
                *(float2*)&C[(size_t)row * N + col] = v0;
                *(float2*)&C[(size_t)(row + 8) * N + col] = v1;
            } else {  // mode 2: eprojT[(t*512 + col)*32 + b]
                int t0 = row >> 5, b0v_ = row & 31;
                int t1 = (row + 8) >> 5, b1v_ = (row + 8) & 31;
                C[((size_t)t0 * 512 + col)     * 32 + b0v_] = v0.x;
                C[((size_t)t0 * 512 + col + 1) * 32 + b0v_] = v0.y;
                C[((size_t)t1 * 512 + col)     * 32 + b1v_] = v1.x;
                C[((size_t)t1 * 512 + col + 1) * 32 + b1v_] = v1.y;
            }
        }
    }
}

// ============ dedicated logits GEMM: 256x128 tile, fp16 2-pass ===============
// C[(b,t,col)] = ysH[M=2048,K=512] @ WdT[N=32000,K=512]^T + bias, remapped
constexpr int LGSZ = (256 + 128 + 128) * LDSg;   // halfs per stage = 20480
constexpr int LOGITS_DSM_BYTES = 2 * LGSZ * 2;   // 81920 B

__global__ __launch_bounds__(256, 1) void mma_logits_kernel(
    const __half* __restrict__ A,
    const __half* __restrict__ Bh, const __half* __restrict__ Bl,
    float* __restrict__ C, const float* __restrict__ bias)
{
    extern __shared__ __align__(16) char dsm[];
    __half* sb = (__half*)dsm;
    const uint32_t sbase = smem_u32(sb);
    const int K = H_;

    const int tid = threadIdx.x, lane = tid & 31, wid = tid >> 5;
    const int wm = wid >> 1, wn = wid & 1;           // wm 0..3, wn 0..1
    const int n0 = blockIdx.x * 128, m0 = blockIdx.y * 256;

    float acc[4][8][4];
#pragma unroll
    for (int i = 0; i < 4; i++)
#pragma unroll
        for (int j = 0; j < 8; j++)
#pragma unroll
            for (int k = 0; k < 4; k++) acc[i][j][k] = 0.f;

    const int lrow = tid >> 2;        // 0..63
    const int lcol = (tid & 3) * 8;
    const int nch = K >> 5;           // 16

    auto issue = [&](int kc, int st) {
        const int kb = kc << 5;
#pragma unroll
        for (int h = 0; h < 4; h++) {                 // A: 256 rows
            int row = lrow + h * 64;
            const __half* pa = A + (size_t)(m0 + row) * K + kb + lcol;
            CPA16(sbase + (uint32_t)(st * LGSZ + row * LDSg + lcol) * 2, pa);
        }
#pragma unroll
        for (int h = 0; h < 2; h++) {                 // B: 128 rows, hi+lo
            int row = lrow + h * 64;
            const __half* pb = Bh + (size_t)(n0 + row) * K + kb + lcol;
            const __half* pq = Bl + (size_t)(n0 + row) * K + kb + lcol;
            uint32_t d = sbase + (uint32_t)(st * LGSZ + (256 + row) * LDSg + lcol) * 2;
            CPA16(d,                 pb);
            CPA16(d + 128 * LDSg * 2, pq);
        }
        CP_COMMIT();
    };

    issue(0, 0);
    for (int kc = 0; kc < nch; kc++) {
        const int st = kc & 1;
        if (kc + 1 < nch) {
            issue(kc + 1, st ^ 1);
            CP_WAIT1();
        } else {
            CP_WAIT0();
        }
        __syncthreads();
        __half* sA  = sb + st * LGSZ;
        __half* sBh = sA + 256 * LDSg;
        __half* sBl = sA + 384 * LDSg;

#pragma unroll
        for (int ks = 0; ks < BKg; ks += 16) {
            uint32_t ah[4][4];
            const uint32_t fcol = ks + (lane >> 4) * 8;
#pragma unroll
            for (int mi = 0; mi < 4; mi++) {
                uint32_t arow = wm * 64 + mi * 16 + (lane & 15);
                ldsm4(ah[mi], smem_u32(&sA[arow * LDSg + fcol]));
            }
#pragma unroll
            for (int nj = 0; nj < 4; nj++) {
                uint32_t brow = wn * 64 + nj * 16 + (lane & 15);
                uint32_t bh[4], bl[4];
                ldsm4(bh, smem_u32(&sBh[brow * LDSg + fcol]));
                ldsm4(bl, smem_u32(&sBl[brow * LDSg + fcol]));
#pragma unroll
                for (int mi = 0; mi < 4; mi++) {
                    mma16816(acc[mi][2 * nj],     ah[mi], bh[0], bh[2]);
                    mma16816(acc[mi][2 * nj + 1], ah[mi], bh[1], bh[3]);
                    mma16816(acc[mi][2 * nj],     ah[mi], bl[0], bl[2]);
                    mma16816(acc[mi][2 * nj + 1], ah[mi], bl[1], bl[3]);
                }
            }
        }
        __syncthreads();
    }

#pragma unroll
    for (int mi = 0; mi < 4; mi++) {
        int row = m0 + wm * 64 + mi * 16 + (lane >> 2);
#pragma unroll
        for (int nt = 0; nt < 8; nt++) {
            int col = n0 + wn * 64 + nt * 8 + (lane & 3) * 2;
            float bb0 = bias[col];
            float bb1 = bias[col + 1];
            float2 v0 = make_float2(acc[mi][nt][0] + bb0, acc[mi][nt][1] + bb1);
            float2 v1 = make_float2(acc[mi][nt][2] + bb0, acc[mi][nt][3] + bb1);
            int t0 = row >> 5, b0v_ = row & 31;
            int t1 = (row + 8) >> 5, b1v_ = (row + 8) & 31;
            *(float2*)&C[(size_t)b0v_ * (TD * V_) + (size_t)t0 * V_ + col] = v0;
            *(float2*)&C[(size_t)b1v_ * (TD * V_) + (size_t)t1 * V_ + col] = v1;
        }
    }
}

// fp32 SIMT GEMM body (512x512x512, transposed write) for Wcomb^T
__device__ void sgemm_tr_body(float* As, float* Bs,
    const float* __restrict__ A, const float* __restrict__ B,
    float* __restrict__ C, int bx, int by)
{
    const int tid = threadIdx.x;
    const float* Aptr = A + (size_t)(by * 128 + (tid >> 1)) * 512 + (tid & 1) * 4;
    const float* Bptr = B + (size_t)(tid >> 5) * 512 + bx * 128 + (tid & 31) * 4;
    const int ty = tid >> 4, tx = tid & 15;
    float acc[8][8];
#pragma unroll
    for (int i = 0; i < 8; i++)
#pragma unroll
        for (int j = 0; j < 8; j++) acc[i][j] = 0.f;
    for (int k0 = 0; k0 < 512; k0 += 8) {
        float4 av = *(const float4*)(Aptr + k0);
        float4 bv = *(const float4*)(Bptr + (size_t)k0 * 512);
        __syncthreads();
        const int ar_ = tid >> 1, ac_ = (tid & 1) * 4;
        As[(ac_ + 0) * 132 + ar_] = av.x; As[(ac_ + 1) * 132 + ar_] = av.y;
        As[(ac_ + 2) * 132 + ar_] = av.z; As[(ac_ + 3) * 132 + ar_] = av.w;
        *(float4*)&Bs[(tid >> 5) * 132 + (tid & 31) * 4] = bv;
        __syncthreads();
#pragma unroll
        for (int kk = 0; kk < 8; kk++) {
            float ar[8], br[8];
            *(float4*)(ar)     = *(float4*)&As[kk * 132 + ty * 4];
            *(float4*)(ar + 4) = *(float4*)&As[kk * 132 + ty * 4 + 64];
            *(float4*)(br)     = *(float4*)&Bs[kk * 132 + tx * 4];
            *(float4*)(br + 4) = *(float4*)&Bs[kk * 132 + tx * 4 + 64];
#pragma unroll
            for (int i = 0; i < 8; i++)
#pragma unroll
                for (int j = 0; j < 8; j++) acc[i][j] += ar[i] * br[j];
        }
    }
#pragma unroll
    for (int i = 0; i < 8; i++) {
        int m = by * 128 + ty * 4 + (i & 3) + (i >> 2) * 64;
#pragma unroll
        for (int j = 0; j < 8; j++) {
            int n = bx * 128 + tx * 4 + (j & 3) + (j >> 2) * 64;
            C[(size_t)n * 512 + m] = acc[i][j];
        }
    }
}

__global__ __launch_bounds__(256, 2) void mma_batched_kernel(
    const __half* __restrict__ encH,
    const __half* __restrict__ WkH,  const __half* __restrict__ WkL,
    const __half* __restrict__ WvH,  const __half* __restrict__ WvL,
    const __half* __restrict__ esH,  const __half* __restrict__ esL,
    const __half* __restrict__ WinH, const __half* __restrict__ WinL,
    float* __restrict__ Kh, float* __restrict__ Vh, float* __restrict__ eprojT,
    const float* __restrict__ Wo, const float* __restrict__ Win,
    float* __restrict__ WcombT)
{
    extern __shared__ __align__(16) char dsm[];
    int z = blockIdx.z;
    if (z == 0) {
        mma_gemm_body(dsm, B_ * TE, H_, 2 * H_,
                      encH, nullptr, WkH, WkL, Kh, nullptr, 0, blockIdx.x, blockIdx.y, 2);
    } else if (z == 1) {
        mma_gemm_body(dsm, B_ * TE, H_, 2 * H_,
                      encH, nullptr, WvH, WvL, Vh, nullptr, 0, blockIdx.x, blockIdx.y, 2);
    } else if (z == 2) {
        if (blockIdx.y >= (TD * B_) / 128) return;
        mma_gemm_body(dsm, TD * B_, H_, E_,
                      esH, esL, WinH, WinL, eprojT, nullptr, 2, blockIdx.x, blockIdx.y, 3);
    } else {
        if (blockIdx.x >= 4 || blockIdx.y >= 4) return;
        sgemm_tr_body((float*)dsm, (float*)dsm + 1056, Wo, Win, WcombT,
                      blockIdx.x, blockIdx.y);
    }
}

// ---------------- fused prep -------------------------------------------------
__device__ void tconv_body(const float* __restrict__ W, int K, int N, int row_off,
                           __half* __restrict__ oh, __half* __restrict__ ol,
                           int bxx, int byy, float* t)
{
    int tx = threadIdx.x & 31, ty = threadIdx.x >> 5;
    int n0 = bxx * 32, k0 = byy * 32;
    for (int ky = ty; ky < 32; ky += 8)
        t[ky * 33 + tx] = W[(size_t)(row_off + k0 + ky) * N + n0 + tx];
    __syncthreads();
    for (int ny = ty; ny < 32; ny += 8) {
        float v = t[tx * 33 + ny];
        __half h, l; hsplit(v, h, l);
        size_t o = (size_t)(n0 + ny) * K + k0 + tx;
        oh[o] = h; ol[o] = l;
    }
}

constexpr int SEG0 = (B_ * TE * 2 * H_) / 4 / 256;   // 8192
constexpr int SEG1 = SEG0 + 512;
constexpr int SEG2 = SEG1 + 512;
constexpr int SEG3 = SEG2 + 256;
constexpr int SEG4 = SEG3 + 16000;
constexpr int SEG5 = SEG4 + 2048;
constexpr int SEG6 = SEG5 + 128;
constexpr int PREP_BLOCKS = SEG6;

__global__ __launch_bounds__(256) void prep_all_kernel(
    const float* __restrict__ enc, const float* __restrict__ Wk,
    const float* __restrict__ Wv, const float* __restrict__ Win,
    const float* __restrict__ Wd, const int* __restrict__ x,
    const float* __restrict__ emb, const float* __restrict__ h0)
{
    __shared__ float t[32 * 33];
    int blk = blockIdx.x, tid = threadIdx.x;
    if (blk == 0 && tid == 0) g_bar = 0;
    if (blk < SEG0) {
        int i = blk * 256 + tid;
        float4 v = ((const float4*)enc)[i];
        ((__half2*)g_enc_h)[2 * i]     = __half2(__float2half_rn(v.x), __float2half_rn(v.y));
        ((__half2*)g_enc_h)[2 * i + 1] = __half2(__float2half_rn(v.z), __float2half_rn(v.w));
    } else if (blk < SEG1) {
        int i = blk - SEG0;
        tconv_body(Wk, 2 * H_, H_, 0, g_Wkt_h, g_Wkt_l, i % 16, i / 16, t);
    } else if (blk < SEG2) {
        int i = blk - SEG1;
        tconv_body(Wv, 2 * H_, H_, 0, g_Wvt_h, g_Wvt_l, i % 16, i / 16, t);
    } else if (blk < SEG3) {
        int i = blk - SEG2;
        tconv_body(Win, H_, H_, 512, g_Wint_h, g_Wint_l, i % 16, i / 16, t);
    } else if (blk < SEG4) {
        int i = blk - SEG3;
        tconv_body(Wd, H_, V_, 0, g_Wdt_h, g_Wdt_l, i % 1000, i / 1000, t);
    } else if (blk < SEG5) {
        int r = blk - SEG4;
        int tt = r >> 5, b = r & 31;
        int tok = x[b * TD + tt];
        const float* src = emb + (size_t)tok * E_;
        for (int i = tid; i < E_; i += 256) {
            __half h, l; hsplit(src[i], h, l);
            g_eseq_h[(size_t)r * E_ + i] = h;
            g_eseq_l[(size_t)r * E_ + i] = l;
        }
    } else {
        int i = (blk - SEG5) * 256 + tid;     // 0..32767 over [l][b][k]
        int l = i >> 14, b = (i >> 9) & 31, k = i & 511;
        float v = h0[i];
        g_hAT[((size_t)l * 512 + k) * 32 + b] = v;
        if (l == 1) g_hA[b * 512 + k] = v;
    }
}

// ---------------- transpose Kh (b,s,h,d) -> Kh2 (b,h,d,s) --------------------
__global__ void transpose_k_kernel()
{
    __shared__ float t[32][33];
    int bh = blockIdx.x;
    int b = bh >> 3, h = bh & 7;
    int s0 = blockIdx.y * 32, d0 = blockIdx.z * 32;
    for (int yy = threadIdx.y; yy < 32; yy += 8)
        t[yy][threadIdx.x] = g_Kh[((size_t)(b * 256 + s0 + yy) * 8 + h) * 64 + d0 + threadIdx.x];
    __syncthreads();
    for (int yy = threadIdx.y; yy < 32; yy += 8)
        g_Kh2[((size_t)(bh) * 64 + d0 + yy) * 256 + s0 + threadIdx.x] = t[threadIdx.x][yy];
}

__global__ void hfinal_kernel(float* __restrict__ dst)
{
    int i = blockIdx.x * blockDim.x + threadIdx.x;
    if (i < LBH) {
        int l = i >> 14, b = (i >> 9) & 31, k = i & 511;
        dst[i] = g_hAT[((size_t)l * 512 + k) * 32 + b];
    }
}

// =================== PERSISTENT SCAN KERNEL (R16 verbatim) ===================
constexpr int OFF_W   = 0;        // 24576: w[l][k][24] (ih gamma-folded)
constexpr int OFF_WC  = 24576;    // 2048:  Wcomb slice [k][4j]
constexpr int OFF_GP  = 26624;    // 6144:  ih/xr partials; attention alias (2x1088)
constexpr int OFF_HH  = 32768;    // 12288: hh partials [l][6144]
constexpr int OFF_GS  = 45056;    // 1024:  stats partials
constexpr int OFF_S   = 46080;    // 24
constexpr int OFF_BC  = 46104;    // 24
constexpr int OFF_SB  = 46128;    // 48
constexpr int SCAN_SMEM_FLOATS = 46208;   // 184832 B

__device__ __forceinline__ void bar_arrive(int& epoch) {
    __syncthreads();
    epoch += NBLK;
    if (threadIdx.x == 0) {
        int* p = &g_bar;
        asm volatile("red.release.gpu.global.add.s32 [%0], 1;" :: "l"(p) : "memory");
    }
}
__device__ __forceinline__ void bar_wait(int epoch) {
    if (threadIdx.x == 0) {
        int* p = &g_bar;
        int v;
        do {
            asm volatile("ld.acquire.gpu.global.s32 %0, [%1];" : "=r"(v) : "l"(p) : "memory");
        } while (v < epoch);
    }
    __syncthreads();
}
__device__ __forceinline__ void grid_bar(int& epoch) {
    bar_arrive(epoch);
    bar_wait(epoch);
}

__global__ __launch_bounds__(NTHR, 1) void scan_kernel(
    const float* __restrict__ Wq,  const int* __restrict__ vlen,
    const float* __restrict__ Wih, const float* __restrict__ Whh,
    const float* __restrict__ bih, const float* __restrict__ bhh,
    const float* __restrict__ lng, const float* __restrict__ lnb,
    const float* __restrict__ alph)
{
    extern __shared__ float sm[];
    float* w    = sm + OFF_W;
    float* wcs  = sm + OFF_WC;
    float* gp   = sm + OFF_GP;
    float* at   = sm + OFF_GP;
    float* gph  = sm + OFF_HH;
    float* gs1  = sm + OFF_GS;
    float* gs2  = sm + OFF_GS + 512;
    float* sS   = sm + OFF_S;
    float* sBc  = sm + OFF_BC;
    float* sbias = sm + OFF_SB;

    const int tid = threadIdx.x, lane = tid & 31, wid = tid >> 5;
    const int blk = blockIdx.x;
    int epoch = 0;

    for (int i = tid; i < 24576; i += NTHR) {
        int unit = i >> 9, k = i & 511;
        int l = unit / 24, idx = unit % 24;
        int pass = idx / 12, r = idx % 12;
        int g = r >> 2, j = r & 3;
        const float* src = (pass == 0)
            ? (Wih + ((size_t)l * 1536 + g * 512 + blk * 4 + j) * 512)
            : (Whh + ((size_t)l * 1536 + g * 512 + blk * 4 + j) * 512);
        w[((l * 512 + k) * 24) + pass * 12 + g * 4 + j] = src[k];
    }
    for (int i = tid; i < 2048; i += NTHR) {
        int k = i >> 2, j = i & 3;
        wcs[i] = g_Wcombt[(size_t)(blk * 4 + j) * 512 + k];
    }
    if (tid < 48) {
        int l = tid / 24, r = tid % 24;
        int j = r / 6, g6 = r % 6;
        int jg = blk * 4 + j;
        sbias[tid] = (g6 < 3) ? bih[l * 1536 + g6 * 512 + jg]
                              : bhh[l * 1536 + (g6 - 3) * 512 + jg];
    }
    __syncthreads();
    if (tid < 24) {
        int l = tid / 12, idx = tid % 12;
        float s = 0.f, bc = 0.f;
        for (int k = 0; k < 512; k++) {
            float rw = w[((l * 512 + k) * 24) + idx];
            s  += lng[l * 512 + k] * rw;
            bc += lnb[l * 512 + k] * rw;
        }
        sS[tid] = s;
        sBc[tid] = bc;
    }
    __syncthreads();
    for (int i = tid; i < 12288; i += NTHR) {
        int l = i / 6144, r = i % 6144;
        int k = r / 12, idx = r % 12;
        w[((l * 512 + k) * 24) + idx] *= lng[l * 512 + k];
    }
    __syncthreads();

    for (int t = 0; t < TD; t++) {
        const float* hinRow = (t & 1) ? g_hB : g_hA;
        float*       houtRow = (t & 1) ? g_hA : g_hB;
        const float* hinT  = (t & 1) ? g_hBT : g_hAT;
        float*       houtT = (t & 1) ? g_hAT : g_hBT;

        // ================= phase 1: attention ================================
        {
            int grp = tid >> 8, lt = tid & 255;
            int u = blk * 2 + grp;
            int b = u >> 3, h = u & 7;
            float* sh_ = at + grp * 1088;
            float* sq_ = sh_ + 512;
            float* sp_ = sq_ + 64;
            float* rd_ = sp_ + 256;
            const float* hlast = hinRow + b * 512;

            sh_[lt] = hlast[lt];
            sh_[lt + 256] = hlast[lt + 256];
            __syncthreads();

            int d = lt & 63, c = lt >> 6;
            {
                float a0 = 0.f, a1 = 0.f;
                const float* wq = Wq + h * 64 + d;
#pragma unroll 8
                for (int k = c * 128; k < c * 128 + 128; k += 2) {
                    a0 += sh_[k]     * wq[(size_t)k * 512];
                    a1 += sh_[k + 1] * wq[(size_t)(k + 1) * 512];
                }
                rd_[lt] = a0 + a1;
            }
            __syncthreads();
            if (lt < 64) sq_[lt] = rd_[lt] + rd_[lt + 64] + rd_[lt + 128] + rd_[lt + 192];
            __syncthreads();

            float sc = -1e6f;
            int vl = vlen[b];
            if (lt < vl) {
                float a0 = 0.f, a1 = 0.f;
                const float* kp = g_Kh2 + (size_t)u * 64 * 256 + lt;
#pragma unroll 8
                for (int dd = 0; dd < 64; dd += 2) {
                    a0 += sq_[dd]     * kp[dd * 256];
                    a1 += sq_[dd + 1] * kp[(dd + 1) * 256];
                }
                sc = (a0 + a1) * 0.125f;
            }
            int wg = lt >> 5;
            float m = sc;
#pragma unroll
            for (int o = 16; o; o >>= 1) m = fmaxf(m, __shfl_xor_sync(0xffffffffu, m, o));
            if ((lt & 31) == 0) rd_[wg] = m;
            __syncthreads();
            float mx = rd_[0];
#pragma unroll
            for (int i = 1; i < 8; i++) mx = fmaxf(mx, rd_[i]);
            float p = __expf(sc - mx);
            float s = p;
#pragma unroll
            for (int o = 16; o; o >>= 1) s += __shfl_xor_sync(0xffffffffu, s, o);
            if ((lt & 31) == 0) rd_[8 + wg] = s;
            __syncthreads();
            float sum = rd_[8];
#pragma unroll
            for (int i = 1; i < 8; i++) sum += rd_[8 + i];
            sp_[lt] = p / sum;
            __syncthreads();

            {
                int lim = vl - c * 64;
                if (lim > 64) lim = 64;
                float a0 = 0.f, a1 = 0.f;
                const float* vp = g_Vh + ((size_t)(b * 256 + c * 64) * 8 + h) * 64 + d;
                int ss = 0;
#pragma unroll 4
                for (; ss + 1 < lim; ss += 2) {
                    a0 += sp_[c * 64 + ss]     * vp[(size_t)ss * 512];
                    a1 += sp_[c * 64 + ss + 1] * vp[(size_t)(ss + 1) * 512];
                }
                if (ss < lim) a0 += sp_[c * 64 + ss] * vp[(size_t)ss * 512];
                rd_[lt] = a0 + a1;
            }
            __syncthreads();
            if (lt < 64)
                g_ctxT[(h * 64 + lt) * 32 + b] =
                    rd_[lt] + rd_[lt + 64] + rd_[lt + 128] + rd_[lt + 192];
        }
        bar_arrive(epoch);

        // ===== overlap window: hh matvecs for BOTH layers (depend on hinT) ==
        {
            const int kc = wid * 32;
#pragma unroll
            for (int l = 0; l < 2; l++) {
                const float* hTl = hinT + (size_t)l * 512 * 32;
                float acc[12];
#pragma unroll
                for (int i = 0; i < 12; i++) acc[i] = 0.f;
                const float* wrow = w + ((size_t)(l * 512 + kc) * 24) + 12;
#pragma unroll 8
                for (int kk = 0; kk < 32; kk++) {
                    float xv = hTl[(kc + kk) * 32 + lane];
                    float4 w0 = *(const float4*)(wrow + kk * 24 + 0);
                    float4 w1 = *(const float4*)(wrow + kk * 24 + 4);
                    float4 w2 = *(const float4*)(wrow + kk * 24 + 8);
                    acc[0] += w0.x * xv; acc[1] += w0.y * xv; acc[2] += w0.z * xv; acc[3] += w0.w * xv;
                    acc[4] += w1.x * xv; acc[5] += w1.y * xv; acc[6] += w1.z * xv; acc[7] += w1.w * xv;
                    acc[8] += w2.x * xv; acc[9] += w2.y * xv; acc[10] += w2.z * xv; acc[11] += w2.w * xv;
                }
#pragma unroll
                for (int i = 0; i < 12; i++)
                    gph[l * 6144 + (wid * 12 + i) * 32 + lane] = acc[i];
            }
        }
        bar_wait(epoch);

        // ================= phase 2: xr = ctx @ Wcomb + eprojT ===============
        {
            int kc = wid * 32;
            float a0 = 0.f, a1 = 0.f, a2 = 0.f, a3 = 0.f;
#pragma unroll 8
            for (int kk = 0; kk < 32; kk++) {
                int k = kc + kk;
                float xv = g_ctxT[k * 32 + lane];
                float4 wv = *(const float4*)(wcs + k * 4);
                a0 += wv.x * xv; a1 += wv.y * xv; a2 += wv.z * xv; a3 += wv.w * xv;
            }
            gp[(wid * 4 + 0) * 32 + lane] = a0;
            gp[(wid * 4 + 1) * 32 + lane] = a1;
            gp[(wid * 4 + 2) * 32 + lane] = a2;
            gp[(wid * 4 + 3) * 32 + lane] = a3;
        }
        __syncthreads();
        if (tid < 128) {
            int j = tid >> 5, b = tid & 31, jg = blk * 4 + j;
            float v = 0.f;
#pragma unroll
            for (int w2 = 0; w2 < 16; w2++) v += gp[(w2 * 4 + j) * 32 + b];
            v += g_eprojT[((size_t)t * 512 + jg) * 32 + b];
            g_xraT[jg * 32 + b] = v;
        }
        grid_bar(epoch);

        // ================= phases 3,4: GRU layers (ih + combine only) =======
        for (int l = 0; l < 2; l++) {
            const float* xrT = (l == 0) ? g_xraT : g_xrbT;
            const float* hTl = hinT + (size_t)l * 512 * 32;
            float* hToutl = houtT + (size_t)l * 512 * 32;

            const int kc = wid * 32;
            {
                float acc[12];
#pragma unroll
                for (int i = 0; i < 12; i++) acc[i] = 0.f;
                float s1 = 0.f, s2 = 0.f;
                const float* wrow = w + ((size_t)(l * 512 + kc) * 24);
#pragma unroll 8
                for (int kk = 0; kk < 32; kk++) {
                    float xv = xrT[(kc + kk) * 32 + lane];
                    s1 += xv; s2 += xv * xv;
                    float4 w0 = *(const float4*)(wrow + kk * 24 + 0);
                    float4 w1 = *(const float4*)(wrow + kk * 24 + 4);
                    float4 w2 = *(const float4*)(wrow + kk * 24 + 8);
                    acc[0] += w0.x * xv; acc[1] += w0.y * xv; acc[2] += w0.z * xv; acc[3] += w0.w * xv;
                    acc[4] += w1.x * xv; acc[5] += w1.y * xv; acc[6] += w1.z * xv; acc[7] += w1.w * xv;
                    acc[8] += w2.x * xv; acc[9] += w2.y * xv; acc[10] += w2.z * xv; acc[11] += w2.w * xv;
                }
#pragma unroll
                for (int i = 0; i < 12; i++)
                    gp[(wid * 12 + i) * 32 + lane] = acc[i];
                gs1[wid * 32 + lane] = s1;
                gs2[wid * 32 + lane] = s2;
            }
            __syncthreads();
            if (tid < 128) {
                int j = tid >> 5, b = tid & 31, jg = blk * 4 + j;
                float s1 = 0.f, s2 = 0.f;
#pragma unroll
                for (int w2 = 0; w2 < 16; w2++) {
                    s1 += gs1[w2 * 32 + b];
                    s2 += gs2[w2 * 32 + b];
                }
                float mu = s1 * (1.f / 512.f);
                float var = s2 * (1.f / 512.f) - mu * mu;
                float rsv = rsqrtf(var + 1e-5f);

                float Dir = 0.f, Diz = 0.f, Dig = 0.f, hr = 0.f, hz = 0.f, hg = 0.f;
#pragma unroll
                for (int w2 = 0; w2 < 16; w2++) {
                    const float* g0 = gp + (w2 * 12) * 32 + b;
                    const float* g1 = gph + l * 6144 + (w2 * 12) * 32 + b;
                    Dir += g0[(0 * 4 + j) * 32];
                    Diz += g0[(1 * 4 + j) * 32];
                    Dig += g0[(2 * 4 + j) * 32];
                    hr  += g1[(0 * 4 + j) * 32];
                    hz  += g1[(1 * 4 + j) * 32];
                    hg  += g1[(2 * 4 + j) * 32];
                }
                const float* bb = sbias + l * 24 + j * 6;
                float rm = rsv * mu;
                float ir = rsv * Dir - rm * sS[l * 12 + 0 * 4 + j] + sBc[l * 12 + 0 * 4 + j] + bb[0];
                float iz = rsv * Diz - rm * sS[l * 12 + 1 * 4 + j] + sBc[l * 12 + 1 * 4 + j] + bb[1];
                float ig = rsv * Dig - rm * sS[l * 12 + 2 * 4 + j] + sBc[l * 12 + 2 * 4 + j] + bb[2];
                hr += bb[3];
                hz += bb[4];
                hg += bb[5];

                float r = fsig(ir + hr);
                float z = fsig(iz + hz);
                float g = ftanh(ig + r * hg);
                float hprev = hTl[jg * 32 + b];
                float hn = (1.f - z) * g + z * hprev;
                hToutl[jg * 32 + b] = hn;
                if (l == 1) houtRow[b * 512 + jg] = hn;
                float yv = xrT[jg * 32 + b] + alph[l] * hn;
                if (l == 0) {
                    g_xrbT[jg * 32 + b] = yv;
                } else {
                    g_ys_h[(size_t)(t * B_ + b) * 512 + jg] = __float2half_rn(yv);
                }
            }
            grid_bar(epoch);
        }
    }
}

// ============================ host orchestration ============================
extern "C" void kernel_launch(void* const* d_in, const int* in_sizes, int n_in,
                              void* d_out, int out_size)
{
    const int*   x    = (const int*)  d_in[0];
    const float* enc  = (const float*)d_in[1];
    const float* h0   = (const float*)d_in[2];
    const int*   vlen = (const int*)  d_in[3];
    const float* emb  = (const float*)d_in[4];
    const float* Wq   = (const float*)d_in[5];
    const float* Wk   = (const float*)d_in[6];
    const float* Wv   = (const float*)d_in[7];
    const float* Wo   = (const float*)d_in[8];
    const float* Win  = (const float*)d_in[9];
    const float* lng  = (const float*)d_in[10];
    const float* lnb  = (const float*)d_in[11];
    const float* alph = (const float*)d_in[12];
    const float* Wih  = (const float*)d_in[13];
    const float* Whh  = (const float*)d_in[14];
    const float* bih  = (const float*)d_in[15];
    const float* bhh  = (const float*)d_in[16];
    const float* Wd   = (const float*)d_in[17];
    const float* bd   = (const float*)d_in[18];
    float* out = (float*)d_out;

    cudaFuncSetAttribute(scan_kernel, cudaFuncAttributeMaxDynamicSharedMemorySize,
                         SCAN_SMEM_FLOATS * 4);
    cudaFuncSetAttribute(mma_batched_kernel, cudaFuncAttributeMaxDynamicSharedMemorySize,
                         GEMM_DSM_BYTES);
    cudaFuncSetAttribute(mma_logits_kernel, cudaFuncAttributeMaxDynamicSharedMemorySize,
                         LOGITS_DSM_BYTES);

    float *pKh, *pVh, *pEprojT, *pWcombT;
    __half *pEncH, *pWktH, *pWktL, *pWvtH, *pWvtL, *pWintH, *pWintL;
    __half *pWdtH, *pWdtL, *pEsH, *pEsL, *pYsH;
    cudaGetSymbolAddress((void**)&pKh,     g_Kh);
    cudaGetSymbolAddress((void**)&pVh,     g_Vh);
    cudaGetSymbolAddress((void**)&pEprojT, g_eprojT);
    cudaGetSymbolAddress((void**)&pWcombT, g_Wcombt);
    cudaGetSymbolAddress((void**)&pEncH,   g_enc_h);
    cudaGetSymbolAddress((void**)&pWktH,   g_Wkt_h);
    cudaGetSymbolAddress((void**)&pWktL,   g_Wkt_l);
    cudaGetSymbolAddress((void**)&pWvtH,   g_Wvt_h);
    cudaGetSymbolAddress((void**)&pWvtL,   g_Wvt_l);
    cudaGetSymbolAddress((void**)&pWintH,  g_Wint_h);
    cudaGetSymbolAddress((void**)&pWintL,  g_Wint_l);
    cudaGetSymbolAddress((void**)&pWdtH,   g_Wdt_h);
    cudaGetSymbolAddress((void**)&pWdtL,   g_Wdt_l);
    cudaGetSymbolAddress((void**)&pEsH,    g_eseq_h);
    cudaGetSymbolAddress((void**)&pEsL,    g_eseq_l);
    cudaGetSymbolAddress((void**)&pYsH,    g_ys_h);

    // launch 0: fused prep
    prep_all_kernel<<<PREP_BLOCKS, 256>>>(enc, Wk, Wv, Win, Wd, x, emb, h0);

    // launch 1: batched K/V (fp16 2-pass) + eprojT (3-pass) + Wcomb^T sgemm
    mma_batched_kernel<<<dim3(4, 64, 4), 256, GEMM_DSM_BYTES>>>(
        pEncH, pWktH, pWktL, pWvtH, pWvtL,
        pEsH, pEsL, pWintH, pWintL, pKh, pVh, pEprojT,
        Wo, Win, pWcombT);

    // launch 2: Kh transpose
    transpose_k_kernel<<<dim3(B_ * NH, TE / 32, DH / 32), dim3(32, 8)>>>();

    // launch 3: the whole 64-step scan (R16 verbatim)
    scan_kernel<<<NBLK, NTHR, SCAN_SMEM_FLOATS * 4>>>(
        Wq, vlen, Wih, Whh, bih, bhh, lng, lnb, alph);

    // launch 4: logits (256x128 tile, fp16 2-pass), transposed write to (B,T,V)
    mma_logits_kernel<<<dim3(V_ / 128, (TD * B_) / 256), 256, LOGITS_DSM_BYTES>>>(
        pYsH, pWdtH, pWdtL, out, bd);

    // launch 5: final hidden state (t=63 odd -> final state in g_hAT)
    if (out_size >= BTV + LBH)
        hfinal_kernel<<<(LBH + 255) / 256, 256>>>(out + BTV);
}